// round 3
// baseline (speedup 1.0000x reference)
#include <cuda_runtime.h>
#include <math.h>
#include <utility>

#define BATCH 32
#define D 256
#define CIN 2048
#define M 784
#define NNS 11
#define NPOW 10

// conv kernel tiles
#define BM 128
#define BN 128
#define BK 8

typedef unsigned long long ull;

// ---------------- scratch (device globals) ---------------------------------
__device__ float g_Z[BATCH * D * M];        // conv acts; later X (expm)
__device__ float g_cov[BATCH * D * D];
__device__ float g_Y[BATCH * D * D];        // Anorm
__device__ float g_Y2[BATCH * D * D];
__device__ float g_Zm[BATCH * D * D];
__device__ float g_Z2[BATCH * D * D];
__device__ float g_T[BATCH * D * D];        // NS temp; later P
__device__ float g_E[BATCH * D * D];
__device__ float g_E2[BATCH * D * D];
__device__ float g_mu[D];
__device__ float g_rstd[D];
__device__ float g_rmean[BATCH * D];
__device__ float g_tau[BATCH];
__device__ float g_stau[BATCH];
__device__ float g_nrm[BATCH];

// ---------------- packed f32x2 FMA -----------------------------------------
__device__ __forceinline__ void ffma2(ull &c, ull a, ull b) {
    asm("fma.rn.f32x2 %0, %1, %2, %0;" : "+l"(c) : "l"(a), "l"(b));
}
__device__ __forceinline__ float2 u2f(ull u) {
    float2 f; asm("mov.b64 {%0, %1}, %2;" : "=f"(f.x), "=f"(f.y) : "l"(u)); return f;
}

// ===========================================================================
// Multi-op 64x64-tile GEMM over 256x256 outputs (C always [b,256,256]).
// flags: 1=TRANSB (B[n][k]), 2=NSFIRST (C=1.5A-0.5*acc, C2=1.5I-0.5A),
//        4=COV (acc/M - rm[m]*rm[n], rmean in aux)
// ===========================================================================
struct OpDesc {
    const float* A; const float* B; float* C; const float* aux; // aux: C2 or rmean
    const float* alphaDev;
    long long sA, sB;
    float alpha, gamma;
    int K, ldab, flags;
};

__global__ __launch_bounds__(128, 4)
void gemm_ops(OpDesc o0, OpDesc o1, OpDesc o2) {
    __shared__ float2 As2[2][16][64];
    __shared__ float  Bs[2][16][64];

    const int zz  = blockIdx.z;
    const int opi = zz >> 5;
    const OpDesc& o = (opi == 0) ? o0 : ((opi == 1) ? o1 : o2);
    const int b  = zz & 31;
    const int t  = threadIdx.x;
    const int tx = t & 15;
    const int ty = t >> 4;
    const int n0 = blockIdx.x * 64;
    const int m0 = blockIdx.y * 64;

    const int lda = o.ldab;
    const bool trans = (o.flags & 1);

    const float* Ag = o.A + (long long)b * o.sA + (size_t)(m0 + (t >> 1)) * lda + ((t & 1) << 2);
    const float* Bg;
    if (!trans)
        Bg = o.B + (long long)b * o.sB + (size_t)(t >> 3) * lda + n0 + ((t & 7) << 3);
    else
        Bg = o.B + (long long)b * o.sB + (size_t)(n0 + (t >> 1)) * lda + ((t & 1) << 2);

    ull acc[8][2];
#pragma unroll
    for (int i = 0; i < 8; ++i) { acc[i][0] = 0ULL; acc[i][1] = 0ULL; }

    const int PNL = o.K >> 4;   // K multiple of 16

    float4 a0 = *(const float4*)Ag;
    float4 a1 = *(const float4*)(Ag + 8);
    float4 b0, b1;
    if (!trans) { b0 = *(const float4*)Bg; b1 = *(const float4*)(Bg + 4); }
    else        { b0 = *(const float4*)Bg; b1 = *(const float4*)(Bg + 8); }

    // store panel 0
    {
        const int m = t >> 1, kc = (t & 1) << 2;
        float av0[4] = {a0.x, a0.y, a0.z, a0.w};
        float av1[4] = {a1.x, a1.y, a1.z, a1.w};
#pragma unroll
        for (int j = 0; j < 4; ++j) {
            As2[0][kc + j][m]     = make_float2(av0[j], av0[j]);
            As2[0][kc + 8 + j][m] = make_float2(av1[j], av1[j]);
        }
        if (!trans) {
            *(float4*)&Bs[0][t >> 3][(t & 7) << 3]       = b0;
            *(float4*)&Bs[0][t >> 3][((t & 7) << 3) + 4] = b1;
        } else {
            float bv0[4] = {b0.x, b0.y, b0.z, b0.w};
            float bv1[4] = {b1.x, b1.y, b1.z, b1.w};
#pragma unroll
            for (int j = 0; j < 4; ++j) {
                Bs[0][kc + j][m]     = bv0[j];
                Bs[0][kc + 8 + j][m] = bv1[j];
            }
        }
    }
    __syncthreads();

    for (int p = 0; p < PNL; ++p) {
        const int buf = p & 1;
        if (p + 1 < PNL) {
            const int ko = (p + 1) << 4;
            a0 = *(const float4*)(Ag + ko);
            a1 = *(const float4*)(Ag + ko + 8);
            if (!trans) {
                const float* bp = Bg + (size_t)ko * lda;
                b0 = *(const float4*)bp; b1 = *(const float4*)(bp + 4);
            } else {
                b0 = *(const float4*)(Bg + ko); b1 = *(const float4*)(Bg + ko + 8);
            }
        }
#pragma unroll
        for (int k = 0; k < 16; ++k) {
            ulonglong2 A01 = *(const ulonglong2*)&As2[buf][k][ty * 4];
            ulonglong2 A23 = *(const ulonglong2*)&As2[buf][k][ty * 4 + 2];
            ulonglong2 A45 = *(const ulonglong2*)&As2[buf][k][32 + ty * 4];
            ulonglong2 A67 = *(const ulonglong2*)&As2[buf][k][32 + ty * 4 + 2];
            ulonglong2 Bv  = *(const ulonglong2*)&Bs[buf][k][tx * 4];
            ull ad[8] = {A01.x, A01.y, A23.x, A23.y, A45.x, A45.y, A67.x, A67.y};
#pragma unroll
            for (int i = 0; i < 8; ++i) {
                ffma2(acc[i][0], ad[i], Bv.x);
                ffma2(acc[i][1], ad[i], Bv.y);
            }
        }
        if (p + 1 < PNL) {
            const int nb = (p + 1) & 1;
            const int m = t >> 1, kc = (t & 1) << 2;
            float av0[4] = {a0.x, a0.y, a0.z, a0.w};
            float av1[4] = {a1.x, a1.y, a1.z, a1.w};
#pragma unroll
            for (int j = 0; j < 4; ++j) {
                As2[nb][kc + j][m]     = make_float2(av0[j], av0[j]);
                As2[nb][kc + 8 + j][m] = make_float2(av1[j], av1[j]);
            }
            if (!trans) {
                *(float4*)&Bs[nb][t >> 3][(t & 7) << 3]       = b0;
                *(float4*)&Bs[nb][t >> 3][((t & 7) << 3) + 4] = b1;
            } else {
                float bv0[4] = {b0.x, b0.y, b0.z, b0.w};
                float bv1[4] = {b1.x, b1.y, b1.z, b1.w};
#pragma unroll
                for (int j = 0; j < 4; ++j) {
                    Bs[nb][kc + j][m]     = bv0[j];
                    Bs[nb][kc + 8 + j][m] = bv1[j];
                }
            }
        }
        __syncthreads();
    }

    // ---------------- epilogue ----------------
    const long long DDll = (long long)D * D;
    float* Cb = o.C + (long long)b * DDll;
    const int n = n0 + tx * 4;
    const float aeff = o.alpha * (o.alphaDev ? o.alphaDev[b] : 1.f);

    if (o.flags & 4) {
        const float* rm = o.aux + b * D;
        const float rn0 = rm[n], rn1 = rm[n + 1], rn2 = rm[n + 2], rn3 = rm[n + 3];
        const float invM = 1.f / (float)M;
#pragma unroll
        for (int i = 0; i < 8; ++i) {
            const int m = m0 + ((i < 4) ? ty * 4 + i : 32 + ty * 4 + (i - 4));
            float2 lo = u2f(acc[i][0]), hi = u2f(acc[i][1]);
            const float rmm = rm[m];
            float4 v = make_float4(lo.x * invM - rmm * rn0, lo.y * invM - rmm * rn1,
                                   hi.x * invM - rmm * rn2, hi.y * invM - rmm * rn3);
            *(float4*)&Cb[(size_t)m * D + n] = v;
        }
    } else if (o.flags & 2) {
        float* C2b = (float*)o.aux + (long long)b * DDll;
        const float* Ab = o.A + (long long)b * o.sA;
#pragma unroll
        for (int i = 0; i < 8; ++i) {
            const int m = m0 + ((i < 4) ? ty * 4 + i : 32 + ty * 4 + (i - 4));
            float2 lo = u2f(acc[i][0]), hi = u2f(acc[i][1]);
            float4 a4 = *(const float4*)&Ab[(size_t)m * D + n];
            float4 y = make_float4(1.5f * a4.x - 0.5f * lo.x, 1.5f * a4.y - 0.5f * lo.y,
                                   1.5f * a4.z - 0.5f * hi.x, 1.5f * a4.w - 0.5f * hi.y);
            float4 zv = make_float4(-0.5f * a4.x, -0.5f * a4.y, -0.5f * a4.z, -0.5f * a4.w);
            if (m == n)     zv.x += 1.5f;
            if (m == n + 1) zv.y += 1.5f;
            if (m == n + 2) zv.z += 1.5f;
            if (m == n + 3) zv.w += 1.5f;
            *(float4*)&Cb[(size_t)m * D + n]  = y;
            *(float4*)&C2b[(size_t)m * D + n] = zv;
        }
    } else {
#pragma unroll
        for (int i = 0; i < 8; ++i) {
            const int m = m0 + ((i < 4) ? ty * 4 + i : 32 + ty * 4 + (i - 4));
            float2 lo = u2f(acc[i][0]), hi = u2f(acc[i][1]);
            float4 v = make_float4(aeff * lo.x, aeff * lo.y, aeff * hi.x, aeff * hi.y);
            if (o.gamma != 0.f) {
                if (m == n)     v.x += o.gamma;
                if (m == n + 1) v.y += o.gamma;
                if (m == n + 2) v.z += o.gamma;
                if (m == n + 3) v.w += o.gamma;
            }
            *(float4*)&Cb[(size_t)m * D + n] = v;
        }
    }
}

// ===========================================================================
// conv 1x1 as GEMM (128x128 tiles) — same as round 2
// ===========================================================================
__global__ __launch_bounds__(256, 2)
void conv_gemm(const float* __restrict__ A, const float* __restrict__ B,
               float* __restrict__ C) {
    __shared__ float2 As2s[2 * BK * BM];
    __shared__ float  Bss[2 * BK * BN];
    const int t  = threadIdx.x;
    const int tx = t & 15;
    const int ty = t >> 4;
    const int z  = blockIdx.z;
    const int n0 = blockIdx.x * BN;
    const int m0 = blockIdx.y * BM;

    const float* Ag = A + (size_t)(m0 + (t >> 1)) * CIN + ((t & 1) << 2);
    const int nB = (t & 31) << 2;
    const bool nOK = (n0 + nB) < M;
    const float* Bg = B + (long long)z * CIN * M + (size_t)(t >> 5) * M + n0 + nB;

    const float4 f4z = make_float4(0.f, 0.f, 0.f, 0.f);
    float4 aReg = *(const float4*)Ag;
    float4 bReg = nOK ? *(const float4*)Bg : f4z;

    ull acc[8][4];
#pragma unroll
    for (int i = 0; i < 8; ++i)
#pragma unroll
        for (int j = 0; j < 4; ++j) acc[i][j] = 0ULL;

    const int PNL = CIN / BK;
    {
        float av[4] = {aReg.x, aReg.y, aReg.z, aReg.w};
#pragma unroll
        for (int j = 0; j < 4; ++j)
            As2s[(4 * (t & 1) + j) * BM + (t >> 1)] = make_float2(av[j], av[j]);
        *(float4*)&Bss[(t >> 5) * BN + nB] = bReg;
    }
    __syncthreads();

    for (int p = 0; p < PNL; ++p) {
        const int buf = p & 1;
        if (p + 1 < PNL) {
            aReg = *(const float4*)(Ag + (size_t)(p + 1) * BK);
            bReg = nOK ? *(const float4*)(Bg + (size_t)(p + 1) * BK * M) : f4z;
        }
        const float2* Ak = As2s + buf * BK * BM;
        const float*  Bk = Bss + buf * BK * BN;
#pragma unroll
        for (int k = 0; k < BK; ++k) {
            const float2* Ar = Ak + k * BM;
            const float*  Br = Bk + k * BN;
            ulonglong2 A0 = *(const ulonglong2*)(Ar + ty * 4);
            ulonglong2 A1 = *(const ulonglong2*)(Ar + ty * 4 + 2);
            ulonglong2 A2 = *(const ulonglong2*)(Ar + ty * 4 + 64);
            ulonglong2 A3 = *(const ulonglong2*)(Ar + ty * 4 + 66);
            ulonglong2 B0 = *(const ulonglong2*)(Br + tx * 4);
            ulonglong2 B1 = *(const ulonglong2*)(Br + tx * 4 + 64);
            ull ad[8] = {A0.x, A0.y, A1.x, A1.y, A2.x, A2.y, A3.x, A3.y};
            ull bp[4] = {B0.x, B0.y, B1.x, B1.y};
#pragma unroll
            for (int i = 0; i < 8; ++i)
#pragma unroll
                for (int j = 0; j < 4; ++j) ffma2(acc[i][j], ad[i], bp[j]);
        }
        if (p + 1 < PNL) {
            float av[4] = {aReg.x, aReg.y, aReg.z, aReg.w};
            const int nb = buf ^ 1;
#pragma unroll
            for (int j = 0; j < 4; ++j)
                As2s[(nb * BK + 4 * (t & 1) + j) * BM + (t >> 1)] = make_float2(av[j], av[j]);
            *(float4*)&Bss[(nb * BK + (t >> 5)) * BN + nB] = bReg;
        }
        __syncthreads();
    }

    float* Cb = C + (long long)z * D * M;
#pragma unroll
    for (int i = 0; i < 8; ++i) {
        const int m = m0 + ((i < 4) ? ty * 4 + i : 64 + ty * 4 + (i - 4));
#pragma unroll
        for (int half = 0; half < 2; ++half) {
            const int n = n0 + half * 64 + tx * 4;
            if (n >= M) continue;
            float2 lo = u2f(acc[i][half * 2]);
            float2 hi = u2f(acc[i][half * 2 + 1]);
            *(float4*)&Cb[(size_t)m * M + n] = make_float4(lo.x, lo.y, hi.x, hi.y);
        }
    }
}

// ---------------- BN statistics --------------------------------------------
__global__ void bn_stats(const float* __restrict__ Z, float* __restrict__ mu,
                         float* __restrict__ rstd) {
    const int d = blockIdx.x;
    float s = 0.f, ss = 0.f;
    for (int idx = threadIdx.x; idx < BATCH * M; idx += blockDim.x) {
        int b = idx / M, m = idx % M;
        float v = Z[((size_t)b * D + d) * M + m];
        s += v; ss += v * v;
    }
    __shared__ float rs[256], rss[256];
    rs[threadIdx.x] = s; rss[threadIdx.x] = ss;
    __syncthreads();
    for (int o = 128; o > 0; o >>= 1) {
        if (threadIdx.x < o) { rs[threadIdx.x] += rs[threadIdx.x + o]; rss[threadIdx.x] += rss[threadIdx.x + o]; }
        __syncthreads();
    }
    if (threadIdx.x == 0) {
        const float N = (float)(BATCH * M);
        float mean = rs[0] / N;
        float var = rss[0] / N - mean * mean;
        mu[d] = mean;
        rstd[d] = rsqrtf(var + 1e-5f);
    }
}

// ---------------- BN apply + ReLU + row mean -------------------------------
__global__ void bn_apply(float* __restrict__ Z, const float* __restrict__ mu,
                         const float* __restrict__ rstd, const float* __restrict__ gamma,
                         const float* __restrict__ beta, float* __restrict__ rmean) {
    const int bd = blockIdx.x;
    const int d = bd & (D - 1);
    const float mm = mu[d], r = rstd[d], g = gamma[d], be = beta[d];
    float* row = Z + (size_t)bd * M;
    float s = 0.f;
    for (int i = threadIdx.x; i < M; i += blockDim.x) {
        float v = (row[i] - mm) * r * g + be;
        v = fmaxf(v, 0.f);
        row[i] = v;
        s += v;
    }
    __shared__ float sm[128];
    sm[threadIdx.x] = s;
    __syncthreads();
    for (int o = 64; o > 0; o >>= 1) {
        if (threadIdx.x < o) sm[threadIdx.x] += sm[threadIdx.x + o];
        __syncthreads();
    }
    if (threadIdx.x == 0) rmean[bd] = sm[0] * (1.f / (float)M);
}

// ---------------- power iteration ------------------------------------------
__global__ void power_iter(const float* __restrict__ cov, float* __restrict__ tau,
                           float* __restrict__ stau) {
    const int b = blockIdx.x;
    const float* Cb = cov + (size_t)b * D * D;
    __shared__ float v[D];
    __shared__ float red[256];
    const int t = threadIdx.x;
    v[t] = 1.f;
    __syncthreads();
    float lam = 1.f;
    for (int it = 0; it < NPOW; ++it) {
        float w = 0.f;
#pragma unroll 4
        for (int j = 0; j < D; ++j) w = fmaf(Cb[(size_t)j * D + t], v[j], w);
        red[t] = w * w;
        __syncthreads();
        for (int o = 128; o > 0; o >>= 1) {
            if (t < o) red[t] += red[t + o];
            __syncthreads();
        }
        lam = sqrtf(red[0]);
        v[t] = w / fmaxf(lam, 1e-20f);
        __syncthreads();
    }
    if (t == 0) {
        float l = fmaxf(lam, 1e-12f);
        tau[b] = l;
        stau[b] = sqrtf(l);
    }
}

// ---------------- elementwise helpers --------------------------------------
__global__ void ns_init(const float* __restrict__ cov, const float* __restrict__ tau,
                        float* __restrict__ An) {
    const int b = blockIdx.y, i = blockIdx.x;
    const float it = 1.f / tau[b];
    const size_t off = ((size_t)b * D + i) * D;
    for (int j = threadIdx.x; j < D; j += blockDim.x) An[off + j] = cov[off + j] * it;
}

__global__ void expm_init(const float* __restrict__ cov, float* __restrict__ X,
                          float* __restrict__ E) {
    const int b = blockIdx.y, i = blockIdx.x;
    const size_t off = ((size_t)b * D + i) * D;
    for (int j = threadIdx.x; j < D; j += blockDim.x) {
        float x = cov[off + j] * (-1.f / 64.f);
        X[off + j] = x;
        E[off + j] = 0.2f * x + ((i == j) ? 1.f : 0.f);
    }
}

__global__ void frob_norm(const float* __restrict__ A, float* __restrict__ out) {
    const int b = blockIdx.x;
    const float* Ab = A + (size_t)b * D * D;
    float ss = 0.f;
    for (int i = threadIdx.x; i < D * D; i += 256) {
        float v = Ab[i];
        ss += v * v;
    }
    __shared__ float sm[256];
    sm[threadIdx.x] = ss;
    __syncthreads();
    for (int o = 128; o > 0; o >>= 1) {
        if (threadIdx.x < o) sm[threadIdx.x] += sm[threadIdx.x + o];
        __syncthreads();
    }
    if (threadIdx.x == 0) out[b] = fmaxf(sqrtf(sm[0]), 1e-12f);
}

__global__ void out_triu(const float* __restrict__ Sq, const float* __restrict__ nrm,
                         float* __restrict__ out) {
    const int b = blockIdx.y, i = blockIdx.x;
    const float sc = 1.f + nrm[b];
    const size_t rowoff = (size_t)i * D - (size_t)i * (i - 1) / 2;
    const float* row = Sq + ((size_t)b * D + i) * D;
    float* ob = out + (size_t)b * (D * (D + 1) / 2) + rowoff - i;
    for (int j = i + (int)threadIdx.x; j < D; j += blockDim.x) ob[j] = sc * row[j];
}

// ---------------------------------------------------------------------------
static float* sym_addr(const void* symbol) {
    void* p = nullptr;
    cudaGetSymbolAddress(&p, symbol);
    return (float*)p;
}

static OpDesc mkop(const float* A, const float* B, float* C, float alpha,
                   float gamma, int K, int ldab, int flags,
                   const float* aux = nullptr, const float* alphaDev = nullptr,
                   long long sA = (long long)D * D, long long sB = (long long)D * D) {
    OpDesc o;
    o.A = A; o.B = B; o.C = C; o.aux = aux; o.alphaDev = alphaDev;
    o.sA = sA; o.sB = sB; o.alpha = alpha; o.gamma = gamma;
    o.K = K; o.ldab = ldab; o.flags = flags;
    return o;
}

extern "C" void kernel_launch(void* const* d_in, const int* in_sizes, int n_in,
                              void* d_out, int out_size) {
    const float* x  = (const float*)d_in[0];
    const float* w  = (const float*)d_in[1];
    const float* gm = (const float*)d_in[2];
    const float* bt = (const float*)d_in[3];
    float* out = (float*)d_out;

    float* Z    = sym_addr(g_Z);
    float* cov  = sym_addr(g_cov);
    float* Y    = sym_addr(g_Y);
    float* Y2   = sym_addr(g_Y2);
    float* Zm   = sym_addr(g_Zm);
    float* Z2   = sym_addr(g_Z2);
    float* T    = sym_addr(g_T);
    float* E    = sym_addr(g_E);
    float* E2   = sym_addr(g_E2);
    float* mu   = sym_addr(g_mu);
    float* rstd = sym_addr(g_rstd);
    float* rmn  = sym_addr(g_rmean);
    float* tau  = sym_addr(g_tau);
    float* stau = sym_addr(g_stau);
    float* nrm  = sym_addr(g_nrm);

    const long long DM = (long long)D * M;

    // expm op sequencer: 4 Taylor + 6 squarings, one op per round slot
    float* Xb = Z;          // X = -cov/64 lives in g_Z after activations retire
    float* Ec = E; float* En = E2;
    int expmStage = 0;      // 0..3 Taylor (k=4,3,2,1), 4..9 squarings, 10 done
    auto nextExpmOp = [&](OpDesc* slot) -> bool {
        if (expmStage >= 10) return false;
        if (expmStage < 4) {
            float kinv = 1.f / (float)(4 - expmStage);
            *slot = mkop(Xb, Ec, En, kinv, 1.f, D, D, 0);
        } else {
            *slot = mkop(Ec, Ec, En, 1.f, 0.f, D, D, 0);
        }
        std::swap(Ec, En);
        ++expmStage;
        return true;
    };

    OpDesc dummy = mkop(cov, cov, T, 0.f, 0.f, D, D, 0);

    // 1. conv 1x1
    conv_gemm<<<dim3(7, 2, BATCH), 256>>>(w, x, Z);
    // 2-3. BN
    bn_stats<<<D, 256>>>(Z, mu, rstd);
    bn_apply<<<BATCH * D, 128>>>(Z, mu, rstd, gm, bt, rmn);
    // 4. covariance (new kernel, 512 CTAs)
    {
        OpDesc c = mkop(Z, Z, cov, 1.f, 0.f, M, M, 1 | 4, rmn, nullptr, DM, DM);
        gemm_ops<<<dim3(4, 4, 32), 128>>>(c, dummy, dummy);
    }
    // 5. spectral norm
    power_iter<<<BATCH, 256>>>(cov, tau, stau);
    // 6. inits
    ns_init<<<dim3(D, BATCH), 256>>>(cov, tau, Y);
    expm_init<<<dim3(D, BATCH), 256>>>(cov, Xb, E);

    // 7. slot 1: NSFIRST (S=A^2 -> Y1,Z1) + expm Taylor k=4
    {
        OpDesc ops[3]; int n = 0;
        ops[n++] = mkop(Y, Y, Y2, 1.f, 0.f, D, D, 2, Zm);   // C=Y1(Y2), C2=Z1(Zm)
        if (nextExpmOp(&ops[n])) ++n;
        while (n < 3) ops[n++] = dummy;
        gemm_ops<<<dim3(4, 4, 32 * 2), 128>>>(ops[0], ops[1], ops[2]);
    }
    float *Yc = Y2, *Zc = Zm, *Yn = Y, *Zn = Z2;
    float* Sq = nullptr;

    // 8. NS iterations 2..NNS, expm riding along
    for (int it = 2; it <= NNS; ++it) {
        // slot A: T = 3I - Z@Y (+expm)
        {
            OpDesc ops[3]; int n = 0;
            ops[n++] = mkop(Zc, Yc, T, -1.f, 3.f, D, D, 0);
            if (nextExpmOp(&ops[n])) ++n;
            int nops = n;
            while (n < 3) ops[n++] = dummy;
            gemm_ops<<<dim3(4, 4, 32 * nops), 128>>>(ops[0], ops[1], ops[2]);
        }
        // slot B: Y' (and Z' unless last) (+expm)
        {
            OpDesc ops[3]; int n = 0;
            if (it < NNS) {
                ops[n++] = mkop(Yc, T, Yn, 0.5f, 0.f, D, D, 0);
                ops[n++] = mkop(T, Zc, Zn, 0.5f, 0.f, D, D, 0);
            } else {
                ops[n++] = mkop(Yc, T, Yn, 0.5f, 0.f, D, D, 0, nullptr, stau);
                Sq = Yn;
            }
            if (n < 3 && nextExpmOp(&ops[n])) ++n;
            int nops = n;
            while (n < 3) ops[n++] = dummy;
            gemm_ops<<<dim3(4, 4, 32 * nops), 128>>>(ops[0], ops[1], ops[2]);
            std::swap(Yc, Yn); std::swap(Zc, Zn);
        }
    }
    // drain any remaining expm ops (shouldn't happen: 10 <= 21 slots)
    while (expmStage < 10) {
        OpDesc ops[3]; int n = 0;
        nextExpmOp(&ops[n]); ++n;
        while (n < 3) ops[n++] = dummy;
        gemm_ops<<<dim3(4, 4, 32), 128>>>(ops[0], ops[1], ops[2]);
    }

    // 9. P = Sq @ E -> T (T free now), nrm = ||P||_F
    {
        OpDesc p = mkop(Sq, Ec, T, 1.f, 0.f, D, D, 0);
        gemm_ops<<<dim3(4, 4, 32), 128>>>(p, dummy, dummy);
    }
    frob_norm<<<BATCH, 256>>>(T, nrm);
    // 10. output
    out_triu<<<dim3(D, BATCH), 256>>>(Sq, nrm, out);

    (void)in_sizes; (void)n_in; (void)out_size;
}

// round 4
// speedup vs baseline: 1.1891x; 1.1891x over previous
#include <cuda_runtime.h>
#include <math.h>
#include <utility>

#define BATCH 32
#define D 256
#define CIN 2048
#define M 784
#define NNS 9
#define NPOW 10

#define BM 128
#define BN 128
#define BK 8

typedef unsigned long long ull;

// ---------------- scratch (device globals) ---------------------------------
__device__ float g_Z[BATCH * D * M];        // conv acts; later X (expm)
__device__ float g_cov[BATCH * D * D];
__device__ float g_Y[BATCH * D * D];
__device__ float g_Y2[BATCH * D * D];
__device__ float g_Zm[BATCH * D * D];
__device__ float g_Z2[BATCH * D * D];
__device__ float g_T[BATCH * D * D];
__device__ float g_E[BATCH * D * D];
__device__ float g_E2[BATCH * D * D];
__device__ float g_mu[D];
__device__ float g_rstd[D];
__device__ float g_rmean[BATCH * D];
__device__ float g_tau[BATCH];
__device__ float g_stau[BATCH];
__device__ float g_nrm[BATCH];

// ---------------- packed f32x2 FMA -----------------------------------------
__device__ __forceinline__ void ffma2(ull &c, ull a, ull b) {
    asm("fma.rn.f32x2 %0, %1, %2, %0;" : "+l"(c) : "l"(a), "l"(b));
}
__device__ __forceinline__ float2 u2f(ull u) {
    float2 f; asm("mov.b64 {%0, %1}, %2;" : "=f"(f.x), "=f"(f.y) : "l"(u)); return f;
}

// ===========================================================================
// Multi-op 128x128-tile GEMM over 256x256 outputs.
// flags: 1=TRANSB, 2=NSFIRST (C=1.5A-0.5acc, aux C2=1.5I-0.5A), 4=COV
// grid: (2, 2, 32*nops), 256 threads.
// ===========================================================================
struct OpDesc {
    const float* A; const float* B; float* C; const float* aux;
    const float* alphaDev;
    long long sA, sB;
    float alpha, gamma;
    int K, ldab, flags;
};

__global__ __launch_bounds__(256, 2)
void gemm_ops(OpDesc o0, OpDesc o1, OpDesc o2) {
    __shared__ float2 As2s[2 * BK * BM];   // duplicated A
    __shared__ float  Bss[2 * BK * BN];

    const int zz  = blockIdx.z;
    const int opi = zz >> 5;
    const OpDesc& o = (opi == 0) ? o0 : ((opi == 1) ? o1 : o2);
    const int b  = zz & 31;
    const int t  = threadIdx.x;
    const int tx = t & 15;
    const int ty = t >> 4;
    const int n0 = blockIdx.x * BN;
    const int m0 = blockIdx.y * BM;

    const int lda = o.ldab;
    const bool trans = (o.flags & 1);

    const float* Ag = o.A + (long long)b * o.sA + (size_t)(m0 + (t >> 1)) * lda + ((t & 1) << 2);
    const float* Bg;
    if (!trans)
        Bg = o.B + (long long)b * o.sB + (size_t)(t >> 5) * lda + n0 + ((t & 31) << 2);
    else
        Bg = o.B + (long long)b * o.sB + (size_t)(n0 + (t >> 1)) * lda + ((t & 1) << 2);

    float4 aReg = *(const float4*)Ag;
    float4 bReg = *(const float4*)Bg;

    ull acc[8][4];
#pragma unroll
    for (int i = 0; i < 8; ++i)
#pragma unroll
        for (int j = 0; j < 4; ++j) acc[i][j] = 0ULL;

    const int PNL = o.K / BK;

    // store panel 0
    {
        float av[4] = {aReg.x, aReg.y, aReg.z, aReg.w};
#pragma unroll
        for (int j = 0; j < 4; ++j)
            As2s[(4 * (t & 1) + j) * BM + (t >> 1)] = make_float2(av[j], av[j]);
        if (!trans) {
            *(float4*)&Bss[(t >> 5) * BN + ((t & 31) << 2)] = bReg;
        } else {
            float bv[4] = {bReg.x, bReg.y, bReg.z, bReg.w};
#pragma unroll
            for (int j = 0; j < 4; ++j)
                Bss[(4 * (t & 1) + j) * BN + (t >> 1)] = bv[j];
        }
    }
    __syncthreads();

    for (int p = 0; p < PNL; ++p) {
        const int buf = p & 1;
        if (p + 1 < PNL) {
            aReg = *(const float4*)(Ag + (size_t)(p + 1) * BK);
            if (!trans)
                bReg = *(const float4*)(Bg + (size_t)(p + 1) * BK * lda);
            else
                bReg = *(const float4*)(Bg + (size_t)(p + 1) * BK);
        }
        const float2* Ak = As2s + buf * BK * BM;
        const float*  Bk = Bss + buf * BK * BN;
#pragma unroll
        for (int k = 0; k < BK; ++k) {
            const float2* Ar = Ak + k * BM;
            const float*  Br = Bk + k * BN;
            ulonglong2 A0 = *(const ulonglong2*)(Ar + ty * 4);
            ulonglong2 A1 = *(const ulonglong2*)(Ar + ty * 4 + 2);
            ulonglong2 A2 = *(const ulonglong2*)(Ar + ty * 4 + 64);
            ulonglong2 A3 = *(const ulonglong2*)(Ar + ty * 4 + 66);
            ulonglong2 B0 = *(const ulonglong2*)(Br + tx * 4);
            ulonglong2 B1 = *(const ulonglong2*)(Br + tx * 4 + 64);
            ull ad[8] = {A0.x, A0.y, A1.x, A1.y, A2.x, A2.y, A3.x, A3.y};
            ull bp[4] = {B0.x, B0.y, B1.x, B1.y};
#pragma unroll
            for (int i = 0; i < 8; ++i)
#pragma unroll
                for (int j = 0; j < 4; ++j) ffma2(acc[i][j], ad[i], bp[j]);
        }
        if (p + 1 < PNL) {
            float av[4] = {aReg.x, aReg.y, aReg.z, aReg.w};
            const int nb = buf ^ 1;
#pragma unroll
            for (int j = 0; j < 4; ++j)
                As2s[(nb * BK + 4 * (t & 1) + j) * BM + (t >> 1)] = make_float2(av[j], av[j]);
            if (!trans) {
                *(float4*)&Bss[(nb * BK + (t >> 5)) * BN + ((t & 31) << 2)] = bReg;
            } else {
                float bv[4] = {bReg.x, bReg.y, bReg.z, bReg.w};
#pragma unroll
                for (int j = 0; j < 4; ++j)
                    Bss[(nb * BK + 4 * (t & 1) + j) * BN + (t >> 1)] = bv[j];
            }
        }
        __syncthreads();
    }

    // ---------------- epilogue ----------------
    const long long DDll = (long long)D * D;
    float* Cb = o.C + (long long)b * DDll;
    const float aeff = o.alpha * (o.alphaDev ? o.alphaDev[b] : 1.f);

    if (o.flags & 4) {
        const float* rm = o.aux + b * D;
        const float invM = 1.f / (float)M;
#pragma unroll
        for (int i = 0; i < 8; ++i) {
            const int m = m0 + ((i < 4) ? ty * 4 + i : 64 + ty * 4 + (i - 4));
            const float rmm = rm[m];
#pragma unroll
            for (int half = 0; half < 2; ++half) {
                const int n = n0 + half * 64 + tx * 4;
                float2 lo = u2f(acc[i][half * 2]), hi = u2f(acc[i][half * 2 + 1]);
                float4 v = make_float4(lo.x * invM - rmm * rm[n],
                                       lo.y * invM - rmm * rm[n + 1],
                                       hi.x * invM - rmm * rm[n + 2],
                                       hi.y * invM - rmm * rm[n + 3]);
                *(float4*)&Cb[(size_t)m * D + n] = v;
            }
        }
    } else if (o.flags & 2) {
        float* C2b = (float*)o.aux + (long long)b * DDll;
        const float* Ab = o.A + (long long)b * o.sA;
#pragma unroll
        for (int i = 0; i < 8; ++i) {
            const int m = m0 + ((i < 4) ? ty * 4 + i : 64 + ty * 4 + (i - 4));
#pragma unroll
            for (int half = 0; half < 2; ++half) {
                const int n = n0 + half * 64 + tx * 4;
                float2 lo = u2f(acc[i][half * 2]), hi = u2f(acc[i][half * 2 + 1]);
                float4 a4 = *(const float4*)&Ab[(size_t)m * D + n];
                float4 y = make_float4(1.5f * a4.x - 0.5f * lo.x, 1.5f * a4.y - 0.5f * lo.y,
                                       1.5f * a4.z - 0.5f * hi.x, 1.5f * a4.w - 0.5f * hi.y);
                float4 zv = make_float4(-0.5f * a4.x, -0.5f * a4.y, -0.5f * a4.z, -0.5f * a4.w);
                if (m == n)     zv.x += 1.5f;
                if (m == n + 1) zv.y += 1.5f;
                if (m == n + 2) zv.z += 1.5f;
                if (m == n + 3) zv.w += 1.5f;
                *(float4*)&Cb[(size_t)m * D + n]  = y;
                *(float4*)&C2b[(size_t)m * D + n] = zv;
            }
        }
    } else {
#pragma unroll
        for (int i = 0; i < 8; ++i) {
            const int m = m0 + ((i < 4) ? ty * 4 + i : 64 + ty * 4 + (i - 4));
#pragma unroll
            for (int half = 0; half < 2; ++half) {
                const int n = n0 + half * 64 + tx * 4;
                float2 lo = u2f(acc[i][half * 2]), hi = u2f(acc[i][half * 2 + 1]);
                float4 v = make_float4(aeff * lo.x, aeff * lo.y, aeff * hi.x, aeff * hi.y);
                if (o.gamma != 0.f) {
                    if (m == n)     v.x += o.gamma;
                    if (m == n + 1) v.y += o.gamma;
                    if (m == n + 2) v.z += o.gamma;
                    if (m == n + 3) v.w += o.gamma;
                }
                *(float4*)&Cb[(size_t)m * D + n] = v;
            }
        }
    }
}

// ===========================================================================
// conv 1x1 as GEMM (128x128 tiles)
// ===========================================================================
__global__ __launch_bounds__(256, 2)
void conv_gemm(const float* __restrict__ A, const float* __restrict__ B,
               float* __restrict__ C) {
    __shared__ float2 As2s[2 * BK * BM];
    __shared__ float  Bss[2 * BK * BN];
    const int t  = threadIdx.x;
    const int tx = t & 15;
    const int ty = t >> 4;
    const int z  = blockIdx.z;
    const int n0 = blockIdx.x * BN;
    const int m0 = blockIdx.y * BM;

    const float* Ag = A + (size_t)(m0 + (t >> 1)) * CIN + ((t & 1) << 2);
    const int nB = (t & 31) << 2;
    const bool nOK = (n0 + nB) < M;
    const float* Bg = B + (long long)z * CIN * M + (size_t)(t >> 5) * M + n0 + nB;

    const float4 f4z = make_float4(0.f, 0.f, 0.f, 0.f);
    float4 aReg = *(const float4*)Ag;
    float4 bReg = nOK ? *(const float4*)Bg : f4z;

    ull acc[8][4];
#pragma unroll
    for (int i = 0; i < 8; ++i)
#pragma unroll
        for (int j = 0; j < 4; ++j) acc[i][j] = 0ULL;

    const int PNL = CIN / BK;
    {
        float av[4] = {aReg.x, aReg.y, aReg.z, aReg.w};
#pragma unroll
        for (int j = 0; j < 4; ++j)
            As2s[(4 * (t & 1) + j) * BM + (t >> 1)] = make_float2(av[j], av[j]);
        *(float4*)&Bss[(t >> 5) * BN + nB] = bReg;
    }
    __syncthreads();

    for (int p = 0; p < PNL; ++p) {
        const int buf = p & 1;
        if (p + 1 < PNL) {
            aReg = *(const float4*)(Ag + (size_t)(p + 1) * BK);
            bReg = nOK ? *(const float4*)(Bg + (size_t)(p + 1) * BK * M) : f4z;
        }
        const float2* Ak = As2s + buf * BK * BM;
        const float*  Bk = Bss + buf * BK * BN;
#pragma unroll
        for (int k = 0; k < BK; ++k) {
            const float2* Ar = Ak + k * BM;
            const float*  Br = Bk + k * BN;
            ulonglong2 A0 = *(const ulonglong2*)(Ar + ty * 4);
            ulonglong2 A1 = *(const ulonglong2*)(Ar + ty * 4 + 2);
            ulonglong2 A2 = *(const ulonglong2*)(Ar + ty * 4 + 64);
            ulonglong2 A3 = *(const ulonglong2*)(Ar + ty * 4 + 66);
            ulonglong2 B0 = *(const ulonglong2*)(Br + tx * 4);
            ulonglong2 B1 = *(const ulonglong2*)(Br + tx * 4 + 64);
            ull ad[8] = {A0.x, A0.y, A1.x, A1.y, A2.x, A2.y, A3.x, A3.y};
            ull bp[4] = {B0.x, B0.y, B1.x, B1.y};
#pragma unroll
            for (int i = 0; i < 8; ++i)
#pragma unroll
                for (int j = 0; j < 4; ++j) ffma2(acc[i][j], ad[i], bp[j]);
        }
        if (p + 1 < PNL) {
            float av[4] = {aReg.x, aReg.y, aReg.z, aReg.w};
            const int nb = buf ^ 1;
#pragma unroll
            for (int j = 0; j < 4; ++j)
                As2s[(nb * BK + 4 * (t & 1) + j) * BM + (t >> 1)] = make_float2(av[j], av[j]);
            *(float4*)&Bss[(nb * BK + (t >> 5)) * BN + nB] = bReg;
        }
        __syncthreads();
    }

    float* Cb = C + (long long)z * D * M;
#pragma unroll
    for (int i = 0; i < 8; ++i) {
        const int m = m0 + ((i < 4) ? ty * 4 + i : 64 + ty * 4 + (i - 4));
#pragma unroll
        for (int half = 0; half < 2; ++half) {
            const int n = n0 + half * 64 + tx * 4;
            if (n >= M) continue;
            float2 lo = u2f(acc[i][half * 2]);
            float2 hi = u2f(acc[i][half * 2 + 1]);
            *(float4*)&Cb[(size_t)m * M + n] = make_float4(lo.x, lo.y, hi.x, hi.y);
        }
    }
}

// ---------------- BN statistics --------------------------------------------
__global__ void bn_stats(const float* __restrict__ Z, float* __restrict__ mu,
                         float* __restrict__ rstd) {
    const int d = blockIdx.x;
    float s = 0.f, ss = 0.f;
    for (int idx = threadIdx.x; idx < BATCH * M; idx += blockDim.x) {
        int b = idx / M, m = idx % M;
        float v = Z[((size_t)b * D + d) * M + m];
        s += v; ss += v * v;
    }
    __shared__ float rs[256], rss[256];
    rs[threadIdx.x] = s; rss[threadIdx.x] = ss;
    __syncthreads();
    for (int o = 128; o > 0; o >>= 1) {
        if (threadIdx.x < o) { rs[threadIdx.x] += rs[threadIdx.x + o]; rss[threadIdx.x] += rss[threadIdx.x + o]; }
        __syncthreads();
    }
    if (threadIdx.x == 0) {
        const float N = (float)(BATCH * M);
        float mean = rs[0] / N;
        float var = rss[0] / N - mean * mean;
        mu[d] = mean;
        rstd[d] = rsqrtf(var + 1e-5f);
    }
}

// ---------------- BN apply + ReLU + row mean -------------------------------
__global__ void bn_apply(float* __restrict__ Z, const float* __restrict__ mu,
                         const float* __restrict__ rstd, const float* __restrict__ gamma,
                         const float* __restrict__ beta, float* __restrict__ rmean) {
    const int bd = blockIdx.x;
    const int d = bd & (D - 1);
    const float mm = mu[d], r = rstd[d], g = gamma[d], be = beta[d];
    float* row = Z + (size_t)bd * M;
    float s = 0.f;
    for (int i = threadIdx.x; i < M; i += blockDim.x) {
        float v = (row[i] - mm) * r * g + be;
        v = fmaxf(v, 0.f);
        row[i] = v;
        s += v;
    }
    __shared__ float sm[128];
    sm[threadIdx.x] = s;
    __syncthreads();
    for (int o = 64; o > 0; o >>= 1) {
        if (threadIdx.x < o) sm[threadIdx.x] += sm[threadIdx.x + o];
        __syncthreads();
    }
    if (threadIdx.x == 0) rmean[bd] = sm[0] * (1.f / (float)M);
}

// ---------------- power iteration; tau = lambda_max/2 ----------------------
__global__ void power_iter(const float* __restrict__ cov, float* __restrict__ tau,
                           float* __restrict__ stau) {
    const int b = blockIdx.x;
    const float* Cb = cov + (size_t)b * D * D;
    __shared__ float v[D];
    __shared__ float red[256];
    const int t = threadIdx.x;
    v[t] = 1.f;
    __syncthreads();
    float lam = 1.f;
    for (int it = 0; it < NPOW; ++it) {
        float w = 0.f;
#pragma unroll 4
        for (int j = 0; j < D; ++j) w = fmaf(Cb[(size_t)j * D + t], v[j], w);
        red[t] = w * w;
        __syncthreads();
        for (int o = 128; o > 0; o >>= 1) {
            if (t < o) red[t] += red[t + o];
            __syncthreads();
        }
        lam = sqrtf(red[0]);
        v[t] = w / fmaxf(lam, 1e-20f);
        __syncthreads();
    }
    if (t == 0) {
        float l = fmaxf(lam, 1e-12f) * 0.5f;   // spectrum of cov/tau in (0, 2]
        tau[b] = l;
        stau[b] = sqrtf(l);
    }
}

// ---------------- fused init: Anorm, X, E ----------------------------------
__global__ void init_mats(const float* __restrict__ cov, const float* __restrict__ tau,
                          float* __restrict__ An, float* __restrict__ X,
                          float* __restrict__ E) {
    const int b = blockIdx.y, i = blockIdx.x;
    const float it = 1.f / tau[b];
    const size_t off = ((size_t)b * D + i) * D;
    for (int j = threadIdx.x; j < D; j += blockDim.x) {
        float c = cov[off + j];
        An[off + j] = c * it;
        float x = c * (-1.f / 64.f);
        X[off + j] = x;
        E[off + j] = 0.2f * x + ((i == j) ? 1.f : 0.f);
    }
}

// ---------------- Frobenius norm per batch ---------------------------------
__global__ void frob_norm(const float* __restrict__ A, float* __restrict__ out) {
    const int b = blockIdx.x;
    const float* Ab = A + (size_t)b * D * D;
    float ss = 0.f;
    for (int i = threadIdx.x; i < D * D; i += 256) {
        float v = Ab[i];
        ss += v * v;
    }
    __shared__ float sm[256];
    sm[threadIdx.x] = ss;
    __syncthreads();
    for (int o = 128; o > 0; o >>= 1) {
        if (threadIdx.x < o) sm[threadIdx.x] += sm[threadIdx.x + o];
        __syncthreads();
    }
    if (threadIdx.x == 0) out[b] = fmaxf(sqrtf(sm[0]), 1e-12f);
}

__global__ void out_triu(const float* __restrict__ Sq, const float* __restrict__ nrm,
                         float* __restrict__ out) {
    const int b = blockIdx.y, i = blockIdx.x;
    const float sc = 1.f + nrm[b];
    const size_t rowoff = (size_t)i * D - (size_t)i * (i - 1) / 2;
    const float* row = Sq + ((size_t)b * D + i) * D;
    float* ob = out + (size_t)b * (D * (D + 1) / 2) + rowoff - i;
    for (int j = i + (int)threadIdx.x; j < D; j += blockDim.x) ob[j] = sc * row[j];
}

// ---------------------------------------------------------------------------
static float* sym_addr(const void* symbol) {
    void* p = nullptr;
    cudaGetSymbolAddress(&p, symbol);
    return (float*)p;
}

static OpDesc mkop(const float* A, const float* B, float* C, float alpha,
                   float gamma, int K, int ldab, int flags,
                   const float* aux = nullptr, const float* alphaDev = nullptr,
                   long long sA = (long long)D * D, long long sB = (long long)D * D) {
    OpDesc o;
    o.A = A; o.B = B; o.C = C; o.aux = aux; o.alphaDev = alphaDev;
    o.sA = sA; o.sB = sB; o.alpha = alpha; o.gamma = gamma;
    o.K = K; o.ldab = ldab; o.flags = flags;
    return o;
}

extern "C" void kernel_launch(void* const* d_in, const int* in_sizes, int n_in,
                              void* d_out, int out_size) {
    const float* x  = (const float*)d_in[0];
    const float* w  = (const float*)d_in[1];
    const float* gm = (const float*)d_in[2];
    const float* bt = (const float*)d_in[3];
    float* out = (float*)d_out;

    float* Z    = sym_addr(g_Z);
    float* cov  = sym_addr(g_cov);
    float* Y    = sym_addr(g_Y);
    float* Y2   = sym_addr(g_Y2);
    float* Zm   = sym_addr(g_Zm);
    float* Z2   = sym_addr(g_Z2);
    float* T    = sym_addr(g_T);
    float* E    = sym_addr(g_E);
    float* E2   = sym_addr(g_E2);
    float* mu   = sym_addr(g_mu);
    float* rstd = sym_addr(g_rstd);
    float* rmn  = sym_addr(g_rmean);
    float* tau  = sym_addr(g_tau);
    float* stau = sym_addr(g_stau);
    float* nrm  = sym_addr(g_nrm);

    const long long DM = (long long)D * M;

    // expm op sequencer: 4 Taylor (k=4..1) + 6 squarings
    float* Xb = Z;          // X = -cov/64 reuses g_Z after activations retire
    float* Ec = E; float* En = E2;
    int expmStage = 0;
    auto nextExpmOp = [&](OpDesc* slot) -> bool {
        if (expmStage >= 10) return false;
        if (expmStage < 4) {
            float kinv = 1.f / (float)(4 - expmStage);
            *slot = mkop(Xb, Ec, En, kinv, 1.f, D, D, 0);
        } else {
            *slot = mkop(Ec, Ec, En, 1.f, 0.f, D, D, 0);
        }
        std::swap(Ec, En);
        ++expmStage;
        return true;
    };

    OpDesc dummy = mkop(cov, cov, T, 0.f, 0.f, D, D, 0);

    auto launch = [&](OpDesc* ops, int n) {
        gemm_ops<<<dim3(2, 2, 32 * n), 256>>>(ops[0], n > 1 ? ops[1] : dummy,
                                              n > 2 ? ops[2] : dummy);
    };

    // 1. conv 1x1
    conv_gemm<<<dim3(7, 2, BATCH), 256>>>(w, x, Z);
    // 2-3. BN
    bn_stats<<<D, 256>>>(Z, mu, rstd);
    bn_apply<<<BATCH * D, 128>>>(Z, mu, rstd, gm, bt, rmn);
    // 4. covariance
    {
        OpDesc c = mkop(Z, Z, cov, 1.f, 0.f, M, M, 1 | 4, rmn, nullptr, DM, DM);
        launch(&c, 1);
    }
    // 5. spectral norm -> tau = lam/2
    power_iter<<<BATCH, 256>>>(cov, tau, stau);
    // 6. fused inits (Anorm->Y, X->g_Z, E)
    init_mats<<<dim3(D, BATCH), 256>>>(cov, tau, Y, Xb, E);

    // 7. round 1: NSFIRST (S=A^2 -> Y1,Z1) + expm Taylor k=4
    {
        OpDesc ops[3]; int n = 0;
        ops[n++] = mkop(Y, Y, Y2, 1.f, 0.f, D, D, 2, Zm);
        if (nextExpmOp(&ops[n])) ++n;
        launch(ops, n);
    }
    float *Yc = Y2, *Zc = Zm, *Yn = Y, *Zn = Z2;
    float* Sq = nullptr;

    // 8. NS iterations 2..NNS with expm riders
    for (int it = 2; it <= NNS; ++it) {
        {   // round A: T = 3I - Z@Y (+ rider)
            OpDesc ops[3]; int n = 0;
            ops[n++] = mkop(Zc, Yc, T, -1.f, 3.f, D, D, 0);
            if (nextExpmOp(&ops[n])) ++n;
            launch(ops, n);
        }
        {   // round B
            OpDesc ops[3]; int n = 0;
            if (it < NNS) {
                ops[n++] = mkop(Yc, T, Yn, 0.5f, 0.f, D, D, 0);
                ops[n++] = mkop(T, Zc, Zn, 0.5f, 0.f, D, D, 0);
            } else {
                ops[n++] = mkop(Yc, T, Yn, 0.5f, 0.f, D, D, 0, nullptr, stau);
                Sq = Yn;
                if (nextExpmOp(&ops[n])) ++n;   // last expm stage rides here
            }
            launch(ops, n);
            std::swap(Yc, Yn); std::swap(Zc, Zn);
        }
    }
    // safety drain (no-op for NNS=9: 10 rider slots available)
    while (expmStage < 10) {
        OpDesc ops[3]; int n = 0;
        nextExpmOp(&ops[n]); ++n;
        launch(ops, n);
    }

    // 9. P = Sq @ E -> T, nrm = ||P||_F
    {
        OpDesc p = mkop(Sq, Ec, T, 1.f, 0.f, D, D, 0);
        launch(&p, 1);
    }
    frob_norm<<<BATCH, 256>>>(T, nrm);
    // 10. output
    out_triu<<<dim3(D, BATCH), 256>>>(Sq, nrm, out);

    (void)in_sizes; (void)n_in; (void)out_size;
}

// round 6
// speedup vs baseline: 2.0822x; 1.7511x over previous
#include <cuda_runtime.h>
#include <cuda_bf16.h>
#include <math.h>
#include <utility>
#include <cstdint>

#define BATCH 32
#define D 256
#define CIN 2048
#define M 784
#define NNS 9
#define NPOW 10

typedef unsigned long long ull;
typedef unsigned int u32;

// ---------------- scratch (device globals) ---------------------------------
__device__ float g_Z[BATCH * D * M];        // conv acts; later X (expm)
__device__ float g_cov[BATCH * D * D];
__device__ float g_Y[BATCH * D * D];
__device__ float g_Y2[BATCH * D * D];
__device__ float g_Zm[BATCH * D * D];
__device__ float g_Z2[BATCH * D * D];
__device__ float g_T[BATCH * D * D];
__device__ float g_E[BATCH * D * D];
__device__ float g_E2[BATCH * D * D];
__device__ float g_mu[D];
__device__ float g_rstd[D];
__device__ float g_rmean[BATCH * D];
__device__ float g_tau[BATCH];
__device__ float g_stau[BATCH];
__device__ float g_nrm[BATCH];

// ---------------- helpers ---------------------------------------------------
__device__ __forceinline__ u32 smem_u32(const void* p) {
    u32 a;
    asm("{ .reg .u64 t; cvta.to.shared.u64 t, %1; cvt.u32.u64 %0, t; }" : "=r"(a) : "l"(p));
    return a;
}
__device__ __forceinline__ u32 pack2(float a, float b) {
    __nv_bfloat162 h = __floats2bfloat162_rn(a, b);
    return *reinterpret_cast<u32*>(&h);
}
__device__ __forceinline__ float lo_res(float a) {
    return a - __bfloat162float(__float2bfloat16_rn(a));
}
__device__ __forceinline__ void ldsm4(u32* r, u32 addr) {
    asm volatile("ldmatrix.sync.aligned.m8n8.x4.shared.b16 {%0,%1,%2,%3}, [%4];"
                 : "=r"(r[0]), "=r"(r[1]), "=r"(r[2]), "=r"(r[3]) : "r"(addr));
}
__device__ __forceinline__ void ldsm2(u32* r, u32 addr) {
    asm volatile("ldmatrix.sync.aligned.m8n8.x2.shared.b16 {%0,%1}, [%2];"
                 : "=r"(r[0]), "=r"(r[1]) : "r"(addr));
}
__device__ __forceinline__ void mma_bf16(float* d, const u32* a, const u32* b) {
    asm volatile(
        "mma.sync.aligned.m16n8k16.row.col.f32.bf16.bf16.f32 "
        "{%0,%1,%2,%3}, {%4,%5,%6,%7}, {%8,%9}, {%0,%1,%2,%3};"
        : "+f"(d[0]), "+f"(d[1]), "+f"(d[2]), "+f"(d[3])
        : "r"(a[0]), "r"(a[1]), "r"(a[2]), "r"(a[3]), "r"(b[0]), "r"(b[1]));
}

// ===========================================================================
// HMMA multi-op GEMM. CTA tile 128x128, 8 warps (2x4), warp tile 64x32,
// K chunks of 64, bf16 hi/lo split (3 mma per product), fp32 accum.
// Smem tiles [128][72] bf16 (144B rows -> conflict-free ldmatrix).
// flags: 1 = B global is [K,N] (transposed smem fill; conv)
//        2 = NSFIRST epilogue (C = 1.5A - 0.5acc, aux C2 = 1.5I - 0.5A)
//        4 = COV epilogue (acc/M - rm[m]*rm[n], rmean in aux)
// ===========================================================================
struct OpDesc {
    const float* A; const float* B; float* C; const float* aux; const float* alphaDev;
    long long sA, sB, sC;
    float alpha, gamma;
    int K, lda, ldb, ldc, Ndim, flags;
};

#define TILE_BYTES (128 * 144)
#define OFF_AH 0
#define OFF_AL TILE_BYTES
#define OFF_BH (2 * TILE_BYTES)
#define OFF_BL (3 * TILE_BYTES)
#define SMEM_BYTES (4 * TILE_BYTES)

__global__ void __launch_bounds__(256, 2)
tc_gemm(OpDesc o0, OpDesc o1, OpDesc o2) {
    extern __shared__ char smem[];
    const int zz  = blockIdx.z;
    const int opi = zz >> 5;
    const OpDesc& o = (opi == 0) ? o0 : ((opi == 1) ? o1 : o2);
    const int b    = zz & 31;
    const int t    = threadIdx.x;
    const int wid  = t >> 5;
    const int lane = t & 31;
    const int n0   = blockIdx.x * 128;
    const int m0   = blockIdx.y * 128;

    const u32 sb = smem_u32(smem);
    const float* Ab = o.A + (long long)b * o.sA;
    const float* Bb = o.B + (long long)b * o.sB;

    float acc[4][4][4];
#pragma unroll
    for (int i = 0; i < 4; ++i)
#pragma unroll
        for (int j = 0; j < 4; ++j)
#pragma unroll
            for (int k = 0; k < 4; ++k) acc[i][j][k] = 0.f;

    const int wm = wid & 1;     // warp row (0..1): 64 rows each
    const int wn = wid >> 1;    // warp col (0..3): 32 cols each

    // lane-invariant ldmatrix address components
    const int lA_row = wm * 64 + (lane & 7) + ((lane >> 3) & 1) * 8;
    const u32 lA_cb  = ((lane >> 4) & 1) * 16;
    const int lB_row = wn * 32 + (lane & 7);
    const u32 lB_cb  = ((lane >> 3) & 1) * 16;

    for (int kb = 0; kb < o.K; kb += 64) {
        const int kc = min(64, o.K - kb);
        __syncthreads();   // previous chunk's compute done before refill
        // ---- A tile [m][k] ----
        {
            const int kq4 = (t & 15) << 2;
            const int rg  = t >> 4;
            if (kq4 < kc) {
#pragma unroll
                for (int i = 0; i < 8; ++i) {
                    const int r = rg + i * 16;
                    float4 v = *(const float4*)(Ab + (size_t)(m0 + r) * o.lda + kb + kq4);
                    const u32 off = (u32)(r * 144 + kq4 * 2);
                    *(uint2*)(smem + OFF_AH + off) =
                        make_uint2(pack2(v.x, v.y), pack2(v.z, v.w));
                    *(uint2*)(smem + OFF_AL + off) =
                        make_uint2(pack2(lo_res(v.x), lo_res(v.y)),
                                   pack2(lo_res(v.z), lo_res(v.w)));
                }
            }
        }
        // ---- B tile [n][k] ----
        if (!(o.flags & 1)) {
            const int kq4 = (t & 15) << 2;
            const int rg  = t >> 4;
            if (kq4 < kc) {
#pragma unroll
                for (int i = 0; i < 8; ++i) {
                    const int r = rg + i * 16;
                    float4 v = *(const float4*)(Bb + (size_t)(n0 + r) * o.ldb + kb + kq4);
                    const u32 off = (u32)(r * 144 + kq4 * 2);
                    *(uint2*)(smem + OFF_BH + off) =
                        make_uint2(pack2(v.x, v.y), pack2(v.z, v.w));
                    *(uint2*)(smem + OFF_BL + off) =
                        make_uint2(pack2(lo_res(v.x), lo_res(v.y)),
                                   pack2(lo_res(v.z), lo_res(v.w)));
                }
            }
        } else {
            // B global [K, N] row-major (conv X): transpose to [n][k]
            const int n     = t & 127;
            const int khalf = (t >> 7) * 32;
            const bool ok   = (n0 + n) < o.Ndim;
            const float* Bp = Bb + (size_t)kb * o.ldb + n0 + n;
#pragma unroll
            for (int kq4 = 0; kq4 < 32; kq4 += 4) {
                const int kk = khalf + kq4;
                float v0 = 0.f, v1 = 0.f, v2 = 0.f, v3 = 0.f;
                if (ok) {
                    const float* p = Bp + (size_t)kk * o.ldb;
                    v0 = p[0]; v1 = p[(size_t)o.ldb];
                    v2 = p[(size_t)2 * o.ldb]; v3 = p[(size_t)3 * o.ldb];
                }
                const u32 off = (u32)(n * 144 + kk * 2);
                *(uint2*)(smem + OFF_BH + off) = make_uint2(pack2(v0, v1), pack2(v2, v3));
                *(uint2*)(smem + OFF_BL + off) =
                    make_uint2(pack2(lo_res(v0), lo_res(v1)), pack2(lo_res(v2), lo_res(v3)));
            }
        }
        __syncthreads();

        const int ns = kc >> 4;
        for (int ks = 0; ks < ns; ++ks) {
            const u32 kbyte = (u32)(ks * 32);
            u32 bh[4][2], bl[4][2];
#pragma unroll
            for (int nf = 0; nf < 4; ++nf) {
                const u32 ba = sb + (u32)((lB_row + nf * 8) * 144) + kbyte + lB_cb;
                ldsm2(bh[nf], ba + OFF_BH);
                ldsm2(bl[nf], ba + OFF_BL);
            }
#pragma unroll
            for (int mp = 0; mp < 2; ++mp) {        // mf pairs {0,1}, {2,3}
                u32 ah0[4], al0[4], ah1[4], al1[4];
                const u32 aa0 = sb + (u32)((lA_row + (mp * 2 + 0) * 16) * 144) + kbyte + lA_cb;
                const u32 aa1 = sb + (u32)((lA_row + (mp * 2 + 1) * 16) * 144) + kbyte + lA_cb;
                ldsm4(ah0, aa0 + OFF_AH);
                ldsm4(al0, aa0 + OFF_AL);
                ldsm4(ah1, aa1 + OFF_AH);
                ldsm4(al1, aa1 + OFF_AL);
#pragma unroll
                for (int nf = 0; nf < 4; ++nf) {
                    mma_bf16(acc[mp * 2 + 0][nf], ah0, bh[nf]);
                    mma_bf16(acc[mp * 2 + 0][nf], ah0, bl[nf]);
                    mma_bf16(acc[mp * 2 + 0][nf], al0, bh[nf]);
                    mma_bf16(acc[mp * 2 + 1][nf], ah1, bh[nf]);
                    mma_bf16(acc[mp * 2 + 1][nf], ah1, bl[nf]);
                    mma_bf16(acc[mp * 2 + 1][nf], al1, bh[nf]);
                }
            }
        }
    }

    // ---------------- epilogue ----------------
    const float aeff = o.alpha * (o.alphaDev ? o.alphaDev[b] : 1.f);
    float* Cb = o.C + (long long)b * o.sC;
    const int mb = m0 + wm * 64 + (lane >> 2);
    const int cb = n0 + wn * 32 + (lane & 3) * 2;

#pragma unroll
    for (int mf = 0; mf < 4; ++mf) {
#pragma unroll
        for (int nf = 0; nf < 4; ++nf) {
            const int c  = cb + nf * 8;
            const int r1 = mb + mf * 16;
            const int r2 = r1 + 8;
            float d0 = acc[mf][nf][0], d1 = acc[mf][nf][1];
            float d2 = acc[mf][nf][2], d3 = acc[mf][nf][3];

            if (o.flags & 4) {
                const float* rm = o.aux + b * D;
                const float invM = 1.f / (float)M;
                const float rc0 = rm[c], rc1 = rm[c + 1];
                *(float2*)&Cb[(size_t)r1 * o.ldc + c] =
                    make_float2(d0 * invM - rm[r1] * rc0, d1 * invM - rm[r1] * rc1);
                *(float2*)&Cb[(size_t)r2 * o.ldc + c] =
                    make_float2(d2 * invM - rm[r2] * rc0, d3 * invM - rm[r2] * rc1);
            } else if (o.flags & 2) {
                float* C2b = (float*)o.aux + (long long)b * (long long)(D * D);
                float2 a1 = *(const float2*)&Ab[(size_t)r1 * o.lda + c];
                float2 a2 = *(const float2*)&Ab[(size_t)r2 * o.lda + c];
                *(float2*)&Cb[(size_t)r1 * o.ldc + c] =
                    make_float2(1.5f * a1.x - 0.5f * d0, 1.5f * a1.y - 0.5f * d1);
                *(float2*)&Cb[(size_t)r2 * o.ldc + c] =
                    make_float2(1.5f * a2.x - 0.5f * d2, 1.5f * a2.y - 0.5f * d3);
                float2 z1 = make_float2(-0.5f * a1.x, -0.5f * a1.y);
                float2 z2 = make_float2(-0.5f * a2.x, -0.5f * a2.y);
                if (r1 == c)     z1.x += 1.5f;
                if (r1 == c + 1) z1.y += 1.5f;
                if (r2 == c)     z2.x += 1.5f;
                if (r2 == c + 1) z2.y += 1.5f;
                *(float2*)&C2b[(size_t)r1 * o.ldc + c] = z1;
                *(float2*)&C2b[(size_t)r2 * o.ldc + c] = z2;
            } else {
                if (c >= o.Ndim) continue;
                float2 v1 = make_float2(aeff * d0, aeff * d1);
                float2 v2 = make_float2(aeff * d2, aeff * d3);
                if (o.gamma != 0.f) {
                    if (r1 == c)     v1.x += o.gamma;
                    if (r1 == c + 1) v1.y += o.gamma;
                    if (r2 == c)     v2.x += o.gamma;
                    if (r2 == c + 1) v2.y += o.gamma;
                }
                *(float2*)&Cb[(size_t)r1 * o.ldc + c] = v1;
                *(float2*)&Cb[(size_t)r2 * o.ldc + c] = v2;
            }
        }
    }
}

// ---------------- BN statistics --------------------------------------------
__global__ void bn_stats(const float* __restrict__ Z, float* __restrict__ mu,
                         float* __restrict__ rstd) {
    const int d = blockIdx.x;
    float s = 0.f, ss = 0.f;
    for (int idx = threadIdx.x; idx < BATCH * M; idx += blockDim.x) {
        int b = idx / M, m = idx % M;
        float v = Z[((size_t)b * D + d) * M + m];
        s += v; ss += v * v;
    }
    __shared__ float rs[256], rss[256];
    rs[threadIdx.x] = s; rss[threadIdx.x] = ss;
    __syncthreads();
    for (int o = 128; o > 0; o >>= 1) {
        if (threadIdx.x < o) { rs[threadIdx.x] += rs[threadIdx.x + o]; rss[threadIdx.x] += rss[threadIdx.x + o]; }
        __syncthreads();
    }
    if (threadIdx.x == 0) {
        const float N = (float)(BATCH * M);
        float mean = rs[0] / N;
        float var = rss[0] / N - mean * mean;
        mu[d] = mean;
        rstd[d] = rsqrtf(var + 1e-5f);
    }
}

// ---------------- BN apply + ReLU + row mean -------------------------------
__global__ void bn_apply(float* __restrict__ Z, const float* __restrict__ mu,
                         const float* __restrict__ rstd, const float* __restrict__ gamma,
                         const float* __restrict__ beta, float* __restrict__ rmean) {
    const int bd = blockIdx.x;
    const int d = bd & (D - 1);
    const float mm = mu[d], r = rstd[d], g = gamma[d], be = beta[d];
    float* row = Z + (size_t)bd * M;
    float s = 0.f;
    for (int i = threadIdx.x; i < M; i += blockDim.x) {
        float v = (row[i] - mm) * r * g + be;
        v = fmaxf(v, 0.f);
        row[i] = v;
        s += v;
    }
    __shared__ float sm[128];
    sm[threadIdx.x] = s;
    __syncthreads();
    for (int o = 64; o > 0; o >>= 1) {
        if (threadIdx.x < o) sm[threadIdx.x] += sm[threadIdx.x + o];
        __syncthreads();
    }
    if (threadIdx.x == 0) rmean[bd] = sm[0] * (1.f / (float)M);
}

// ---------------- power iteration; tau = lambda_max/2 ----------------------
__global__ void power_iter(const float* __restrict__ cov, float* __restrict__ tau,
                           float* __restrict__ stau) {
    const int b = blockIdx.x;
    const float* Cb = cov + (size_t)b * D * D;
    __shared__ float v[D];
    __shared__ float red[256];
    const int t = threadIdx.x;
    v[t] = 1.f;
    __syncthreads();
    float lam = 1.f;
    for (int it = 0; it < NPOW; ++it) {
        float w = 0.f;
#pragma unroll 4
        for (int j = 0; j < D; ++j) w = fmaf(Cb[(size_t)j * D + t], v[j], w);
        red[t] = w * w;
        __syncthreads();
        for (int o = 128; o > 0; o >>= 1) {
            if (t < o) red[t] += red[t + o];
            __syncthreads();
        }
        lam = sqrtf(red[0]);
        v[t] = w / fmaxf(lam, 1e-20f);
        __syncthreads();
    }
    if (t == 0) {
        float l = fmaxf(lam, 1e-12f) * 0.5f;
        tau[b] = l;
        stau[b] = sqrtf(l);
    }
}

// ---------------- fused init: Anorm, X, E ----------------------------------
__global__ void init_mats(const float* __restrict__ cov, const float* __restrict__ tau,
                          float* __restrict__ An, float* __restrict__ X,
                          float* __restrict__ E) {
    const int b = blockIdx.y, i = blockIdx.x;
    const float it = 1.f / tau[b];
    const size_t off = ((size_t)b * D + i) * D;
    for (int j = threadIdx.x; j < D; j += blockDim.x) {
        float c = cov[off + j];
        An[off + j] = c * it;
        float x = c * (-1.f / 64.f);
        X[off + j] = x;
        E[off + j] = 0.2f * x + ((i == j) ? 1.f : 0.f);
    }
}

// ---------------- Frobenius norm per batch ---------------------------------
__global__ void frob_norm(const float* __restrict__ A, float* __restrict__ out) {
    const int b = blockIdx.x;
    const float* Ab = A + (size_t)b * D * D;
    float ss = 0.f;
    for (int i = threadIdx.x; i < D * D; i += 256) {
        float v = Ab[i];
        ss += v * v;
    }
    __shared__ float sm[256];
    sm[threadIdx.x] = ss;
    __syncthreads();
    for (int o = 128; o > 0; o >>= 1) {
        if (threadIdx.x < o) sm[threadIdx.x] += sm[threadIdx.x + o];
        __syncthreads();
    }
    if (threadIdx.x == 0) out[b] = fmaxf(sqrtf(sm[0]), 1e-12f);
}

__global__ void out_triu(const float* __restrict__ Sq, const float* __restrict__ nrm,
                         float* __restrict__ out) {
    const int b = blockIdx.y, i = blockIdx.x;
    const float sc = 1.f + nrm[b];
    const size_t rowoff = (size_t)i * D - (size_t)i * (i - 1) / 2;
    const float* row = Sq + ((size_t)b * D + i) * D;
    float* ob = out + (size_t)b * (D * (D + 1) / 2) + rowoff - i;
    for (int j = i + (int)threadIdx.x; j < D; j += blockDim.x) ob[j] = sc * row[j];
}

// ---------------------------------------------------------------------------
static float* sym_addr(const void* symbol) {
    void* p = nullptr;
    cudaGetSymbolAddress(&p, symbol);
    return (float*)p;
}

static OpDesc mkop(const float* A, const float* B, float* C, float alpha,
                   float gamma, int K, int lda, int ldb, int ldc, int Ndim, int flags,
                   const float* aux = nullptr, const float* alphaDev = nullptr,
                   long long sA = (long long)D * D, long long sB = (long long)D * D,
                   long long sC = (long long)D * D) {
    OpDesc o;
    o.A = A; o.B = B; o.C = C; o.aux = aux; o.alphaDev = alphaDev;
    o.sA = sA; o.sB = sB; o.sC = sC;
    o.alpha = alpha; o.gamma = gamma;
    o.K = K; o.lda = lda; o.ldb = ldb; o.ldc = ldc; o.Ndim = Ndim; o.flags = flags;
    return o;
}

extern "C" void kernel_launch(void* const* d_in, const int* in_sizes, int n_in,
                              void* d_out, int out_size) {
    const float* x  = (const float*)d_in[0];
    const float* w  = (const float*)d_in[1];
    const float* gm = (const float*)d_in[2];
    const float* bt = (const float*)d_in[3];
    float* out = (float*)d_out;

    float* Z    = sym_addr(g_Z);
    float* cov  = sym_addr(g_cov);
    float* Y    = sym_addr(g_Y);
    float* Y2   = sym_addr(g_Y2);
    float* Zm   = sym_addr(g_Zm);
    float* Z2   = sym_addr(g_Z2);
    float* T    = sym_addr(g_T);
    float* E    = sym_addr(g_E);
    float* E2   = sym_addr(g_E2);
    float* mu   = sym_addr(g_mu);
    float* rstd = sym_addr(g_rstd);
    float* rmn  = sym_addr(g_rmean);
    float* tau  = sym_addr(g_tau);
    float* stau = sym_addr(g_stau);
    float* nrm  = sym_addr(g_nrm);

    cudaFuncSetAttribute(tc_gemm, cudaFuncAttributeMaxDynamicSharedMemorySize, SMEM_BYTES);

    const long long DM = (long long)D * M;

    // expm op sequencer: 4 Taylor (k=4..1) + 6 squarings
    float* Xb = Z;          // X = -cov/64 reuses g_Z after activations retire
    float* Ec = E; float* En = E2;
    int expmStage = 0;
    auto nextExpmOp = [&](OpDesc* slot) -> bool {
        if (expmStage >= 10) return false;
        if (expmStage < 4) {
            float kinv = 1.f / (float)(4 - expmStage);
            *slot = mkop(Xb, Ec, En, kinv, 1.f, D, D, D, D, D, 0);
        } else {
            *slot = mkop(Ec, Ec, En, 1.f, 0.f, D, D, D, D, D, 0);
        }
        std::swap(Ec, En);
        ++expmStage;
        return true;
    };

    OpDesc dummy = mkop(cov, cov, T, 0.f, 0.f, D, D, D, D, D, 0);

    auto launch = [&](OpDesc* ops, int n) {
        tc_gemm<<<dim3(2, 2, 32 * n), 256, SMEM_BYTES>>>(ops[0], n > 1 ? ops[1] : dummy,
                                                         n > 2 ? ops[2] : dummy);
    };

    // 1. conv 1x1: Z[b,d,m] = sum_c W[d,c] X[b,c,m]  (B = X is [K=2048, N=784])
    {
        OpDesc c = mkop(w, x, Z, 1.f, 0.f, CIN, CIN, M, M, M, 1,
                        nullptr, nullptr, 0LL, (long long)CIN * M, DM);
        tc_gemm<<<dim3(7, 2, 32), 256, SMEM_BYTES>>>(c, dummy, dummy);
    }
    // 2-3. BN
    bn_stats<<<D, 256>>>(Z, mu, rstd);
    bn_apply<<<BATCH * D, 128>>>(Z, mu, rstd, gm, bt, rmn);
    // 4. covariance: cov = Z Z^T / M - rmean rmean^T  (both operands K-major)
    {
        OpDesc c = mkop(Z, Z, cov, 1.f, 0.f, M, M, M, D, D, 4,
                        rmn, nullptr, DM, DM, (long long)D * D);
        launch(&c, 1);
    }
    // 5. spectral norm -> tau = lam/2
    power_iter<<<BATCH, 256>>>(cov, tau, stau);
    // 6. fused inits (Anorm->Y, X->g_Z, E)
    init_mats<<<dim3(D, BATCH), 256>>>(cov, tau, Y, Xb, E);

    // 7. round 1: NSFIRST (S=A^2 -> Y1,Z1) + expm rider
    {
        OpDesc ops[3]; int n = 0;
        ops[n++] = mkop(Y, Y, Y2, 1.f, 0.f, D, D, D, D, D, 2, Zm);
        if (nextExpmOp(&ops[n])) ++n;
        launch(ops, n);
    }
    float *Yc = Y2, *Zc = Zm, *Yn = Y, *Zn = Z2;
    float* Sq = nullptr;

    // 8. NS iterations 2..NNS with expm riders
    for (int it = 2; it <= NNS; ++it) {
        {   // round A: T = 3I - Z@Y (+ rider)
            OpDesc ops[3]; int n = 0;
            ops[n++] = mkop(Zc, Yc, T, -1.f, 3.f, D, D, D, D, D, 0);
            if (nextExpmOp(&ops[n])) ++n;
            launch(ops, n);
        }
        {   // round B
            OpDesc ops[3]; int n = 0;
            if (it < NNS) {
                ops[n++] = mkop(Yc, T, Yn, 0.5f, 0.f, D, D, D, D, D, 0);
                ops[n++] = mkop(T, Zc, Zn, 0.5f, 0.f, D, D, D, D, D, 0);
            } else {
                ops[n++] = mkop(Yc, T, Yn, 0.5f, 0.f, D, D, D, D, D, 0, nullptr, stau);
                Sq = Yn;
                if (nextExpmOp(&ops[n])) ++n;
            }
            launch(ops, n);
            std::swap(Yc, Yn); std::swap(Zc, Zn);
        }
    }
    // safety drain
    while (expmStage < 10) {
        OpDesc ops[3]; int n = 0;
        nextExpmOp(&ops[n]); ++n;
        launch(ops, n);
    }

    // 9. P = Sq @ E -> T, nrm = ||P||_F
    {
        OpDesc p = mkop(Sq, Ec, T, 1.f, 0.f, D, D, D, D, D, 0);
        launch(&p, 1);
    }
    frob_norm<<<BATCH, 256>>>(T, nrm);
    // 10. output
    out_triu<<<dim3(D, BATCH), 256>>>(Sq, nrm, out);

    (void)in_sizes; (void)n_in; (void)out_size;
}

// round 7
// speedup vs baseline: 2.3126x; 1.1106x over previous
#include <cuda_runtime.h>
#include <cuda_bf16.h>
#include <math.h>
#include <utility>
#include <cstdint>

#define BATCH 32
#define D 256
#define CIN 2048
#define M 784
#define NNS 8
#define NPOW 10

typedef unsigned long long ull;
typedef unsigned int u32;

// ---------------- scratch (device globals) ---------------------------------
__device__ float g_Z[BATCH * D * M];        // conv acts; later X (expm)
__device__ float g_cov[BATCH * D * D];
__device__ float g_Y[BATCH * D * D];
__device__ float g_Y2[BATCH * D * D];
__device__ float g_Zm[BATCH * D * D];
__device__ float g_Z2[BATCH * D * D];
__device__ float g_T[BATCH * D * D];
__device__ float g_E[BATCH * D * D];
__device__ float g_E2[BATCH * D * D];
__device__ float g_mu[D];
__device__ float g_rstd[D];
__device__ float g_rmean[BATCH * D];
__device__ float g_tau[BATCH];
__device__ float g_stau[BATCH];
__device__ float g_nrm[BATCH];

// ---------------- helpers ---------------------------------------------------
__device__ __forceinline__ u32 smem_u32(const void* p) {
    u32 a;
    asm("{ .reg .u64 t; cvta.to.shared.u64 t, %1; cvt.u32.u64 %0, t; }" : "=r"(a) : "l"(p));
    return a;
}
__device__ __forceinline__ u32 pack2(float a, float b) {
    __nv_bfloat162 h = __floats2bfloat162_rn(a, b);
    return *reinterpret_cast<u32*>(&h);
}
__device__ __forceinline__ float lo_res(float a) {
    return a - __bfloat162float(__float2bfloat16_rn(a));
}
__device__ __forceinline__ void ldsm4(u32* r, u32 addr) {
    asm volatile("ldmatrix.sync.aligned.m8n8.x4.shared.b16 {%0,%1,%2,%3}, [%4];"
                 : "=r"(r[0]), "=r"(r[1]), "=r"(r[2]), "=r"(r[3]) : "r"(addr));
}
__device__ __forceinline__ void mma_bf16(float* d, const u32* a, const u32* b) {
    asm volatile(
        "mma.sync.aligned.m16n8k16.row.col.f32.bf16.bf16.f32 "
        "{%0,%1,%2,%3}, {%4,%5,%6,%7}, {%8,%9}, {%0,%1,%2,%3};"
        : "+f"(d[0]), "+f"(d[1]), "+f"(d[2]), "+f"(d[3])
        : "r"(a[0]), "r"(a[1]), "r"(a[2]), "r"(a[3]), "r"(b[0]), "r"(b[1]));
}

// ===========================================================================
// HMMA multi-op GEMM. CTA tile 128x64, 8 warps (4x2), warp tile 32x32,
// K chunks of 64, bf16 hi/lo split (3 mma per product), fp32 accum,
// register-prefetch pipeline over chunks.
// flags: 1 = B global is [K,N] (transposed smem fill; conv)
//        2 = NSFIRST epilogue (C = 1.5A - 0.5acc, aux C2 = 1.5I - 0.5A)
//        4 = COV epilogue (acc/M - rm[m]*rm[n], rmean in aux)
// ===========================================================================
struct OpDesc {
    const float* A; const float* B; float* C; const float* aux; const float* alphaDev;
    long long sA, sB, sC;
    float alpha, gamma;
    int K, lda, ldb, ldc, Ndim, flags;
};

#define A_TILE (128 * 144)
#define B_TILE (64 * 144)
#define OFF_AH 0
#define OFF_AL A_TILE
#define OFF_BH (2 * A_TILE)
#define OFF_BL (2 * A_TILE + B_TILE)
#define SMEM_BYTES (2 * A_TILE + 2 * B_TILE)

__global__ void __launch_bounds__(256, 2)
tc_gemm(OpDesc o0, OpDesc o1, OpDesc o2) {
    extern __shared__ char smem[];
    const int zz  = blockIdx.z;
    const int opi = zz >> 5;
    const OpDesc& o = (opi == 0) ? o0 : ((opi == 1) ? o1 : o2);
    const int b    = zz & 31;
    const int t    = threadIdx.x;
    const int wid  = t >> 5;
    const int lane = t & 31;
    const int n0   = blockIdx.x * 64;
    const int m0   = blockIdx.y * 128;

    const u32 sb = smem_u32(smem);
    const float* Ab = o.A + (long long)b * o.sA;
    const float* Bb = o.B + (long long)b * o.sB;
    const bool trans = (o.flags & 1);

    float acc[2][4][4];
#pragma unroll
    for (int i = 0; i < 2; ++i)
#pragma unroll
        for (int j = 0; j < 4; ++j)
#pragma unroll
            for (int k = 0; k < 4; ++k) acc[i][j][k] = 0.f;

    const int wm = wid >> 1;    // warp row 0..3 (32 rows each)
    const int wn = wid & 1;     // warp col 0..1 (32 cols each)

    // ldmatrix lane addressing
    const int lAr = (lane & 7) + ((lane >> 3) & 1) * 8;
    const u32 lAc = ((lane >> 4) & 1) * 16;
    const int lBr = (lane & 7) + ((lane >> 4) & 1) * 8;
    const u32 lBc = ((lane >> 3) & 1) * 16;

    // loader indexing
    const int rgA  = t >> 4;            // 0..15
    const int kq4  = (t & 15) << 2;     // 0..60
    const int cN   = t & 63;            // conv: col within tile
    const int cK0  = (t >> 6) << 4;     // conv: k base (0,16,32,48)
    const bool cOK = (n0 + cN) < o.Ndim;

    float4 pfA[8];
    float4 pfB4[4];
    float* pfBs = (float*)pfB4;

    const int nc = (o.K + 63) >> 6;

    auto prefetch = [&](int c) {
        const int kb = c << 6;
        const int kc = min(64, o.K - kb);
        if (kq4 < kc) {
#pragma unroll
            for (int i = 0; i < 8; ++i)
                pfA[i] = *(const float4*)(Ab + (size_t)(m0 + rgA + i * 16) * o.lda + kb + kq4);
            if (!trans) {
#pragma unroll
                for (int i = 0; i < 4; ++i)
                    pfB4[i] = *(const float4*)(Bb + (size_t)(n0 + rgA + i * 16) * o.ldb + kb + kq4);
            }
        }
        if (trans) {
            const float* Bp = Bb + (size_t)(kb + cK0) * o.ldb + n0 + cN;
#pragma unroll
            for (int j = 0; j < 16; ++j)
                pfBs[j] = cOK ? Bp[(size_t)j * o.ldb] : 0.f;
        }
    };

    prefetch(0);

    for (int c = 0; c < nc; ++c) {
        const int kb = c << 6;
        const int kc = min(64, o.K - kb);
        __syncthreads();    // previous chunk's compute done
        // ---- store prefetched chunk to smem (convert + split) ----
        if (kq4 < kc) {
#pragma unroll
            for (int i = 0; i < 8; ++i) {
                const u32 off = (u32)((rgA + i * 16) * 144 + kq4 * 2);
                float4 v = pfA[i];
                *(uint2*)(smem + OFF_AH + off) = make_uint2(pack2(v.x, v.y), pack2(v.z, v.w));
                *(uint2*)(smem + OFF_AL + off) =
                    make_uint2(pack2(lo_res(v.x), lo_res(v.y)), pack2(lo_res(v.z), lo_res(v.w)));
            }
            if (!trans) {
#pragma unroll
                for (int i = 0; i < 4; ++i) {
                    const u32 off = (u32)((rgA + i * 16) * 144 + kq4 * 2);
                    float4 v = pfB4[i];
                    *(uint2*)(smem + OFF_BH + off) = make_uint2(pack2(v.x, v.y), pack2(v.z, v.w));
                    *(uint2*)(smem + OFF_BL + off) =
                        make_uint2(pack2(lo_res(v.x), lo_res(v.y)), pack2(lo_res(v.z), lo_res(v.w)));
                }
            }
        }
        if (trans) {
#pragma unroll
            for (int j = 0; j < 4; ++j) {
                const u32 off = (u32)(cN * 144 + (cK0 + j * 4) * 2);
                float v0 = pfBs[j * 4], v1 = pfBs[j * 4 + 1];
                float v2 = pfBs[j * 4 + 2], v3 = pfBs[j * 4 + 3];
                *(uint2*)(smem + OFF_BH + off) = make_uint2(pack2(v0, v1), pack2(v2, v3));
                *(uint2*)(smem + OFF_BL + off) =
                    make_uint2(pack2(lo_res(v0), lo_res(v1)), pack2(lo_res(v2), lo_res(v3)));
            }
        }
        __syncthreads();
        // ---- prefetch next chunk (latency hidden by MMAs below) ----
        if (c + 1 < nc) prefetch(c + 1);
        // ---- compute ----
        const int ns = kc >> 4;
        for (int ks = 0; ks < ns; ++ks) {
            const u32 kbyte = (u32)(ks * 32);
            u32 bh[2][4], bl[2][4];     // [pair][4 regs] -> frags {2pr, 2pr+1}
#pragma unroll
            for (int pr = 0; pr < 2; ++pr) {
                const u32 ba = sb + (u32)((wn * 32 + pr * 16 + lBr) * 144) + kbyte + lBc;
                ldsm4(bh[pr], ba + OFF_BH);
                ldsm4(bl[pr], ba + OFF_BL);
            }
#pragma unroll
            for (int mf = 0; mf < 2; ++mf) {
                u32 ah[4], al[4];
                const u32 aa = sb + (u32)((wm * 32 + mf * 16 + lAr) * 144) + kbyte + lAc;
                ldsm4(ah, aa + OFF_AH);
                ldsm4(al, aa + OFF_AL);
#pragma unroll
                for (int nf = 0; nf < 4; ++nf) {
                    const u32* bhf = &bh[nf >> 1][(nf & 1) * 2];
                    const u32* blf = &bl[nf >> 1][(nf & 1) * 2];
                    mma_bf16(acc[mf][nf], ah, bhf);
                    mma_bf16(acc[mf][nf], ah, blf);
                    mma_bf16(acc[mf][nf], al, bhf);
                }
            }
        }
    }

    // ---------------- epilogue ----------------
    const float aeff = o.alpha * (o.alphaDev ? o.alphaDev[b] : 1.f);
    float* Cb = o.C + (long long)b * o.sC;
    const int mb = m0 + wm * 32 + (lane >> 2);
    const int cb = n0 + wn * 32 + (lane & 3) * 2;

#pragma unroll
    for (int mf = 0; mf < 2; ++mf) {
#pragma unroll
        for (int nf = 0; nf < 4; ++nf) {
            const int c  = cb + nf * 8;
            const int r1 = mb + mf * 16;
            const int r2 = r1 + 8;
            float d0 = acc[mf][nf][0], d1 = acc[mf][nf][1];
            float d2 = acc[mf][nf][2], d3 = acc[mf][nf][3];

            if (o.flags & 4) {
                const float* rm = o.aux + b * D;
                const float invM = 1.f / (float)M;
                const float rc0 = rm[c], rc1 = rm[c + 1];
                *(float2*)&Cb[(size_t)r1 * o.ldc + c] =
                    make_float2(d0 * invM - rm[r1] * rc0, d1 * invM - rm[r1] * rc1);
                *(float2*)&Cb[(size_t)r2 * o.ldc + c] =
                    make_float2(d2 * invM - rm[r2] * rc0, d3 * invM - rm[r2] * rc1);
            } else if (o.flags & 2) {
                float* C2b = (float*)o.aux + (long long)b * (long long)(D * D);
                float2 a1 = *(const float2*)&Ab[(size_t)r1 * o.lda + c];
                float2 a2 = *(const float2*)&Ab[(size_t)r2 * o.lda + c];
                *(float2*)&Cb[(size_t)r1 * o.ldc + c] =
                    make_float2(1.5f * a1.x - 0.5f * d0, 1.5f * a1.y - 0.5f * d1);
                *(float2*)&Cb[(size_t)r2 * o.ldc + c] =
                    make_float2(1.5f * a2.x - 0.5f * d2, 1.5f * a2.y - 0.5f * d3);
                float2 z1 = make_float2(-0.5f * a1.x, -0.5f * a1.y);
                float2 z2 = make_float2(-0.5f * a2.x, -0.5f * a2.y);
                if (r1 == c)     z1.x += 1.5f;
                if (r1 == c + 1) z1.y += 1.5f;
                if (r2 == c)     z2.x += 1.5f;
                if (r2 == c + 1) z2.y += 1.5f;
                *(float2*)&C2b[(size_t)r1 * o.ldc + c] = z1;
                *(float2*)&C2b[(size_t)r2 * o.ldc + c] = z2;
            } else {
                if (c >= o.Ndim) continue;
                float2 v1 = make_float2(aeff * d0, aeff * d1);
                float2 v2 = make_float2(aeff * d2, aeff * d3);
                if (o.gamma != 0.f) {
                    if (r1 == c)     v1.x += o.gamma;
                    if (r1 == c + 1) v1.y += o.gamma;
                    if (r2 == c)     v2.x += o.gamma;
                    if (r2 == c + 1) v2.y += o.gamma;
                }
                *(float2*)&Cb[(size_t)r1 * o.ldc + c] = v1;
                *(float2*)&Cb[(size_t)r2 * o.ldc + c] = v2;
            }
        }
    }
}

// ---------------- BN statistics --------------------------------------------
__global__ void bn_stats(const float* __restrict__ Z, float* __restrict__ mu,
                         float* __restrict__ rstd) {
    const int d = blockIdx.x;
    float s = 0.f, ss = 0.f;
    for (int idx = threadIdx.x; idx < BATCH * M; idx += blockDim.x) {
        int b = idx / M, m = idx % M;
        float v = Z[((size_t)b * D + d) * M + m];
        s += v; ss += v * v;
    }
    __shared__ float rs[256], rss[256];
    rs[threadIdx.x] = s; rss[threadIdx.x] = ss;
    __syncthreads();
    for (int o = 128; o > 0; o >>= 1) {
        if (threadIdx.x < o) { rs[threadIdx.x] += rs[threadIdx.x + o]; rss[threadIdx.x] += rss[threadIdx.x + o]; }
        __syncthreads();
    }
    if (threadIdx.x == 0) {
        const float N = (float)(BATCH * M);
        float mean = rs[0] / N;
        float var = rss[0] / N - mean * mean;
        mu[d] = mean;
        rstd[d] = rsqrtf(var + 1e-5f);
    }
}

// ---------------- BN apply + ReLU + row mean -------------------------------
__global__ void bn_apply(float* __restrict__ Z, const float* __restrict__ mu,
                         const float* __restrict__ rstd, const float* __restrict__ gamma,
                         const float* __restrict__ beta, float* __restrict__ rmean) {
    const int bd = blockIdx.x;
    const int d = bd & (D - 1);
    const float mm = mu[d], r = rstd[d], g = gamma[d], be = beta[d];
    float* row = Z + (size_t)bd * M;
    float s = 0.f;
    for (int i = threadIdx.x; i < M; i += blockDim.x) {
        float v = (row[i] - mm) * r * g + be;
        v = fmaxf(v, 0.f);
        row[i] = v;
        s += v;
    }
    __shared__ float sm[128];
    sm[threadIdx.x] = s;
    __syncthreads();
    for (int o = 64; o > 0; o >>= 1) {
        if (threadIdx.x < o) sm[threadIdx.x] += sm[threadIdx.x + o];
        __syncthreads();
    }
    if (threadIdx.x == 0) rmean[bd] = sm[0] * (1.f / (float)M);
}

// ---------------- power iteration; tau = lambda_max/2 ----------------------
__global__ void power_iter(const float* __restrict__ cov, float* __restrict__ tau,
                           float* __restrict__ stau) {
    const int b = blockIdx.x;
    const float* Cb = cov + (size_t)b * D * D;
    __shared__ float v[D];
    __shared__ float red[256];
    const int t = threadIdx.x;
    v[t] = 1.f;
    __syncthreads();
    float lam = 1.f;
    for (int it = 0; it < NPOW; ++it) {
        float w = 0.f;
#pragma unroll 4
        for (int j = 0; j < D; ++j) w = fmaf(Cb[(size_t)j * D + t], v[j], w);
        red[t] = w * w;
        __syncthreads();
        for (int o = 128; o > 0; o >>= 1) {
            if (t < o) red[t] += red[t + o];
            __syncthreads();
        }
        lam = sqrtf(red[0]);
        v[t] = w / fmaxf(lam, 1e-20f);
        __syncthreads();
    }
    if (t == 0) {
        float l = fmaxf(lam, 1e-12f) * 0.5f;
        tau[b] = l;
        stau[b] = sqrtf(l);
    }
}

// ---------------- fused init: Anorm, X, E ----------------------------------
__global__ void init_mats(const float* __restrict__ cov, const float* __restrict__ tau,
                          float* __restrict__ An, float* __restrict__ X,
                          float* __restrict__ E) {
    const int b = blockIdx.y, i = blockIdx.x;
    const float it = 1.f / tau[b];
    const size_t off = ((size_t)b * D + i) * D;
    for (int j = threadIdx.x; j < D; j += blockDim.x) {
        float c = cov[off + j];
        An[off + j] = c * it;
        float x = c * (-1.f / 64.f);
        X[off + j] = x;
        E[off + j] = 0.2f * x + ((i == j) ? 1.f : 0.f);
    }
}

// ---------------- Frobenius norm per batch ---------------------------------
__global__ void frob_norm(const float* __restrict__ A, float* __restrict__ out) {
    const int b = blockIdx.x;
    const float* Ab = A + (size_t)b * D * D;
    float ss = 0.f;
    for (int i = threadIdx.x; i < D * D; i += 256) {
        float v = Ab[i];
        ss += v * v;
    }
    __shared__ float sm[256];
    sm[threadIdx.x] = ss;
    __syncthreads();
    for (int o = 128; o > 0; o >>= 1) {
        if (threadIdx.x < o) sm[threadIdx.x] += sm[threadIdx.x + o];
        __syncthreads();
    }
    if (threadIdx.x == 0) out[b] = fmaxf(sqrtf(sm[0]), 1e-12f);
}

__global__ void out_triu(const float* __restrict__ Sq, const float* __restrict__ nrm,
                         float* __restrict__ out) {
    const int b = blockIdx.y, i = blockIdx.x;
    const float sc = 1.f + nrm[b];
    const size_t rowoff = (size_t)i * D - (size_t)i * (i - 1) / 2;
    const float* row = Sq + ((size_t)b * D + i) * D;
    float* ob = out + (size_t)b * (D * (D + 1) / 2) + rowoff - i;
    for (int j = i + (int)threadIdx.x; j < D; j += blockDim.x) ob[j] = sc * row[j];
}

// ---------------------------------------------------------------------------
static float* sym_addr(const void* symbol) {
    void* p = nullptr;
    cudaGetSymbolAddress(&p, symbol);
    return (float*)p;
}

static OpDesc mkop(const float* A, const float* B, float* C, float alpha,
                   float gamma, int K, int lda, int ldb, int ldc, int Ndim, int flags,
                   const float* aux = nullptr, const float* alphaDev = nullptr,
                   long long sA = (long long)D * D, long long sB = (long long)D * D,
                   long long sC = (long long)D * D) {
    OpDesc o;
    o.A = A; o.B = B; o.C = C; o.aux = aux; o.alphaDev = alphaDev;
    o.sA = sA; o.sB = sB; o.sC = sC;
    o.alpha = alpha; o.gamma = gamma;
    o.K = K; o.lda = lda; o.ldb = ldb; o.ldc = ldc; o.Ndim = Ndim; o.flags = flags;
    return o;
}

extern "C" void kernel_launch(void* const* d_in, const int* in_sizes, int n_in,
                              void* d_out, int out_size) {
    const float* x  = (const float*)d_in[0];
    const float* w  = (const float*)d_in[1];
    const float* gm = (const float*)d_in[2];
    const float* bt = (const float*)d_in[3];
    float* out = (float*)d_out;

    float* Z    = sym_addr(g_Z);
    float* cov  = sym_addr(g_cov);
    float* Y    = sym_addr(g_Y);
    float* Y2   = sym_addr(g_Y2);
    float* Zm   = sym_addr(g_Zm);
    float* Z2   = sym_addr(g_Z2);
    float* T    = sym_addr(g_T);
    float* E    = sym_addr(g_E);
    float* E2   = sym_addr(g_E2);
    float* mu   = sym_addr(g_mu);
    float* rstd = sym_addr(g_rstd);
    float* rmn  = sym_addr(g_rmean);
    float* tau  = sym_addr(g_tau);
    float* stau = sym_addr(g_stau);
    float* nrm  = sym_addr(g_nrm);

    cudaFuncSetAttribute(tc_gemm, cudaFuncAttributeMaxDynamicSharedMemorySize, SMEM_BYTES);

    const long long DM = (long long)D * M;

    // expm op sequencer: 4 Taylor (k=4..1) + 6 squarings
    float* Xb = Z;          // X = -cov/64 reuses g_Z after activations retire
    float* Ec = E; float* En = E2;
    int expmStage = 0;
    auto nextExpmOp = [&](OpDesc* slot) -> bool {
        if (expmStage >= 10) return false;
        if (expmStage < 4) {
            float kinv = 1.f / (float)(4 - expmStage);
            *slot = mkop(Xb, Ec, En, kinv, 1.f, D, D, D, D, D, 0);
        } else {
            *slot = mkop(Ec, Ec, En, 1.f, 0.f, D, D, D, D, D, 0);
        }
        std::swap(Ec, En);
        ++expmStage;
        return true;
    };

    OpDesc dummy = mkop(cov, cov, T, 0.f, 0.f, D, D, D, D, D, 0);

    auto launch = [&](OpDesc* ops, int n) {
        tc_gemm<<<dim3(4, 2, 32 * n), 256, SMEM_BYTES>>>(ops[0], n > 1 ? ops[1] : dummy,
                                                         n > 2 ? ops[2] : dummy);
    };

    // 1. conv 1x1: Z[b,d,m] = sum_c W[d,c] X[b,c,m]  (B = X is [K=2048, N=784])
    {
        OpDesc c = mkop(w, x, Z, 1.f, 0.f, CIN, CIN, M, M, M, 1,
                        nullptr, nullptr, 0LL, (long long)CIN * M, DM);
        tc_gemm<<<dim3(13, 2, 32), 256, SMEM_BYTES>>>(c, dummy, dummy);
    }
    // 2-3. BN
    bn_stats<<<D, 256>>>(Z, mu, rstd);
    bn_apply<<<BATCH * D, 128>>>(Z, mu, rstd, gm, bt, rmn);
    // 4. covariance: cov = Z Z^T / M - rmean rmean^T  (both operands K-major)
    {
        OpDesc c = mkop(Z, Z, cov, 1.f, 0.f, M, M, M, D, D, 4,
                        rmn, nullptr, DM, DM, (long long)D * D);
        launch(&c, 1);
    }
    // 5. spectral norm -> tau = lam/2
    power_iter<<<BATCH, 256>>>(cov, tau, stau);
    // 6. fused inits (Anorm->Y, X->g_Z, E)
    init_mats<<<dim3(D, BATCH), 256>>>(cov, tau, Y, Xb, E);

    // 7. round 1: NSFIRST (S=A^2 -> Y1,Z1) + expm rider
    {
        OpDesc ops[3]; int n = 0;
        ops[n++] = mkop(Y, Y, Y2, 1.f, 0.f, D, D, D, D, D, 2, Zm);
        if (nextExpmOp(&ops[n])) ++n;
        launch(ops, n);
    }
    float *Yc = Y2, *Zc = Zm, *Yn = Y, *Zn = Z2;
    float* Sq = nullptr;

    // 8. NS iterations 2..NNS with expm riders
    for (int it = 2; it <= NNS; ++it) {
        {   // round A: T = 3I - Z@Y (+ rider)
            OpDesc ops[3]; int n = 0;
            ops[n++] = mkop(Zc, Yc, T, -1.f, 3.f, D, D, D, D, D, 0);
            if (nextExpmOp(&ops[n])) ++n;
            launch(ops, n);
        }
        {   // round B (+ rider)
            OpDesc ops[3]; int n = 0;
            if (it < NNS) {
                ops[n++] = mkop(Yc, T, Yn, 0.5f, 0.f, D, D, D, D, D, 0);
                ops[n++] = mkop(T, Zc, Zn, 0.5f, 0.f, D, D, D, D, D, 0);
            } else {
                ops[n++] = mkop(Yc, T, Yn, 0.5f, 0.f, D, D, D, D, D, 0, nullptr, stau);
                Sq = Yn;
            }
            if (n < 3 && nextExpmOp(&ops[n])) ++n;
            launch(ops, n);
            std::swap(Yc, Yn); std::swap(Zc, Zn);
        }
    }
    // safety drain (should be empty: 15 rider slots >= 10 stages)
    while (expmStage < 10) {
        OpDesc ops[3]; int n = 0;
        nextExpmOp(&ops[n]); ++n;
        launch(ops, n);
    }

    // 9. P = Sq @ E -> T, nrm = ||P||_F
    {
        OpDesc p = mkop(Sq, Ec, T, 1.f, 0.f, D, D, D, D, D, 0);
        launch(&p, 1);
    }
    frob_norm<<<BATCH, 256>>>(T, nrm);
    // 10. output
    out_triu<<<dim3(D, BATCH), 256>>>(Sq, nrm, out);

    (void)in_sizes; (void)n_in; (void)out_size;
}

// round 8
// speedup vs baseline: 2.7095x; 1.1716x over previous
#include <cuda_runtime.h>
#include <cuda_bf16.h>
#include <cuda_fp16.h>
#include <math.h>
#include <utility>
#include <cstdint>

#define BATCH 32
#define D 256
#define CIN 2048
#define M 784
#define NNS 8
#define NPOW 10

typedef unsigned long long ull;
typedef unsigned int u32;

// ---------------- scratch (device globals) ---------------------------------
__device__ float g_Z[BATCH * D * M];        // conv acts fp32; later X (expm)
__device__ __half g_Zh[BATCH * D * M];      // BN+ReLU activations fp16
__device__ float g_cov[BATCH * D * D];
__device__ float g_Y[BATCH * D * D];
__device__ float g_Y2[BATCH * D * D];
__device__ float g_Zm[BATCH * D * D];
__device__ float g_Z2[BATCH * D * D];
__device__ float g_T[BATCH * D * D];
__device__ float g_E[BATCH * D * D];
__device__ float g_E2[BATCH * D * D];
__device__ float g_bnsum[D];
__device__ float g_bnsq[D];
__device__ float g_rmean[BATCH * D];
__device__ float g_tau[BATCH];
__device__ float g_stau[BATCH];
__device__ float g_nrm[BATCH];

// ---------------- helpers ---------------------------------------------------
__device__ __forceinline__ u32 smem_u32(const void* p) {
    u32 a;
    asm("{ .reg .u64 t; cvta.to.shared.u64 t, %1; cvt.u32.u64 %0, t; }" : "=r"(a) : "l"(p));
    return a;
}
__device__ __forceinline__ u32 pack2(float a, float b) {
    __nv_bfloat162 h = __floats2bfloat162_rn(a, b);
    return *reinterpret_cast<u32*>(&h);
}
__device__ __forceinline__ u32 pack2h(float a, float b) {
    __half2 h = __floats2half2_rn(a, b);
    return *reinterpret_cast<u32*>(&h);
}
__device__ __forceinline__ float lo_res(float a) {
    return a - __bfloat162float(__float2bfloat16_rn(a));
}
__device__ __forceinline__ void ldsm4(u32* r, u32 addr) {
    asm volatile("ldmatrix.sync.aligned.m8n8.x4.shared.b16 {%0,%1,%2,%3}, [%4];"
                 : "=r"(r[0]), "=r"(r[1]), "=r"(r[2]), "=r"(r[3]) : "r"(addr));
}
__device__ __forceinline__ void mma_bf16(float* d, const u32* a, const u32* b) {
    asm volatile(
        "mma.sync.aligned.m16n8k16.row.col.f32.bf16.bf16.f32 "
        "{%0,%1,%2,%3}, {%4,%5,%6,%7}, {%8,%9}, {%0,%1,%2,%3};"
        : "+f"(d[0]), "+f"(d[1]), "+f"(d[2]), "+f"(d[3])
        : "r"(a[0]), "r"(a[1]), "r"(a[2]), "r"(a[3]), "r"(b[0]), "r"(b[1]));
}
__device__ __forceinline__ void mma_fp16(float* d, const u32* a, const u32* b) {
    asm volatile(
        "mma.sync.aligned.m16n8k16.row.col.f32.f16.f16.f32 "
        "{%0,%1,%2,%3}, {%4,%5,%6,%7}, {%8,%9}, {%0,%1,%2,%3};"
        : "+f"(d[0]), "+f"(d[1]), "+f"(d[2]), "+f"(d[3])
        : "r"(a[0]), "r"(a[1]), "r"(a[2]), "r"(a[3]), "r"(b[0]), "r"(b[1]));
}

// ===========================================================================
// HMMA multi-op GEMM. CTA tile 128x64, 8 warps (4x2), warp tile 32x32,
// K chunks of 64, register-prefetch pipeline.
// Precision: default bf16 hi/lo split (3 mma); flag 8 = single fp16 mma.
// flags: 1 = B global is [K,N] (transposed smem fill; conv)
//        2 = NSFIRST epilogue  4 = COV epilogue
//        8 = fp16 single-MMA   16 = BN-stats accumulation epilogue
// ===========================================================================
struct OpDesc {
    const float* A; const float* B; float* C; const float* aux; const float* alphaDev;
    long long sA, sB, sC;
    float alpha, gamma;
    int K, lda, ldb, ldc, Ndim, flags;
};

#define A_TILE (128 * 144)
#define B_TILE (64 * 144)
#define OFF_AH 0
#define OFF_AL A_TILE
#define OFF_BH (2 * A_TILE)
#define OFF_BL (2 * A_TILE + B_TILE)
#define SMEM_BYTES (2 * A_TILE + 2 * B_TILE)

__global__ void __launch_bounds__(256, 2)
tc_gemm(OpDesc o0, OpDesc o1, OpDesc o2) {
    extern __shared__ char smem[];
    const int zz  = blockIdx.z;
    const int opi = zz >> 5;
    const OpDesc& o = (opi == 0) ? o0 : ((opi == 1) ? o1 : o2);
    const int b    = zz & 31;
    const int t    = threadIdx.x;
    const int wid  = t >> 5;
    const int lane = t & 31;
    const int n0   = blockIdx.x * 64;
    const int m0   = blockIdx.y * 128;

    const u32 sb = smem_u32(smem);
    const bool trans = (o.flags & 1);
    const bool fp16m = (o.flags & 8);

    const float* Ab = nullptr; const __half* AbH = nullptr;
    const float* Bb = nullptr; const __half* BbH = nullptr;
    if (fp16m && !trans) {
        AbH = (const __half*)o.A + (long long)b * o.sA;
        BbH = (const __half*)o.B + (long long)b * o.sB;
    } else {
        Ab = o.A + (long long)b * o.sA;
        Bb = o.B + (long long)b * o.sB;
    }

    float acc[2][4][4];
#pragma unroll
    for (int i = 0; i < 2; ++i)
#pragma unroll
        for (int j = 0; j < 4; ++j)
#pragma unroll
            for (int k = 0; k < 4; ++k) acc[i][j][k] = 0.f;

    const int wm = wid >> 1;
    const int wn = wid & 1;

    const int lAr = (lane & 7) + ((lane >> 3) & 1) * 8;
    const u32 lAc = ((lane >> 4) & 1) * 16;
    const int lBr = (lane & 7) + ((lane >> 4) & 1) * 8;
    const u32 lBc = ((lane >> 3) & 1) * 16;

    const int rgA  = t >> 4;
    const int kq4  = (t & 15) << 2;
    const int cN   = t & 63;
    const int cK0  = (t >> 6) << 4;
    const bool cOK = (n0 + cN) < o.Ndim;

    float4 pfA[8];
    float4 pfB4[4];
    float* pfBs = (float*)pfB4;

    const int nc = (o.K + 63) >> 6;

    auto prefetch = [&](int c) {
        const int kb = c << 6;
        const int kc = min(64, o.K - kb);
        if (kq4 < kc) {
            if (fp16m && !trans) {
#pragma unroll
                for (int i = 0; i < 8; ++i) {
                    uint2 v = *(const uint2*)(AbH + (size_t)(m0 + rgA + i * 16) * o.lda + kb + kq4);
                    pfA[i].x = __uint_as_float(v.x); pfA[i].y = __uint_as_float(v.y);
                }
#pragma unroll
                for (int i = 0; i < 4; ++i) {
                    uint2 v = *(const uint2*)(BbH + (size_t)(n0 + rgA + i * 16) * o.ldb + kb + kq4);
                    pfB4[i].x = __uint_as_float(v.x); pfB4[i].y = __uint_as_float(v.y);
                }
            } else {
#pragma unroll
                for (int i = 0; i < 8; ++i)
                    pfA[i] = *(const float4*)(Ab + (size_t)(m0 + rgA + i * 16) * o.lda + kb + kq4);
                if (!trans) {
#pragma unroll
                    for (int i = 0; i < 4; ++i)
                        pfB4[i] = *(const float4*)(Bb + (size_t)(n0 + rgA + i * 16) * o.ldb + kb + kq4);
                }
            }
        }
        if (trans) {
            const float* Bp = Bb + (size_t)(kb + cK0) * o.ldb + n0 + cN;
#pragma unroll
            for (int j = 0; j < 16; ++j)
                pfBs[j] = cOK ? Bp[(size_t)j * o.ldb] : 0.f;
        }
    };

    prefetch(0);

    for (int c = 0; c < nc; ++c) {
        const int kb = c << 6;
        const int kc = min(64, o.K - kb);
        __syncthreads();
        // ---- store prefetched chunk ----
        if (kq4 < kc) {
#pragma unroll
            for (int i = 0; i < 8; ++i) {
                const u32 off = (u32)((rgA + i * 16) * 144 + kq4 * 2);
                float4 v = pfA[i];
                if (!fp16m) {
                    *(uint2*)(smem + OFF_AH + off) = make_uint2(pack2(v.x, v.y), pack2(v.z, v.w));
                    *(uint2*)(smem + OFF_AL + off) =
                        make_uint2(pack2(lo_res(v.x), lo_res(v.y)), pack2(lo_res(v.z), lo_res(v.w)));
                } else if (trans) {
                    *(uint2*)(smem + OFF_AH + off) = make_uint2(pack2h(v.x, v.y), pack2h(v.z, v.w));
                } else {
                    *(uint2*)(smem + OFF_AH + off) =
                        make_uint2(__float_as_uint(v.x), __float_as_uint(v.y));
                }
            }
            if (!trans) {
#pragma unroll
                for (int i = 0; i < 4; ++i) {
                    const u32 off = (u32)((rgA + i * 16) * 144 + kq4 * 2);
                    float4 v = pfB4[i];
                    if (!fp16m) {
                        *(uint2*)(smem + OFF_BH + off) = make_uint2(pack2(v.x, v.y), pack2(v.z, v.w));
                        *(uint2*)(smem + OFF_BL + off) =
                            make_uint2(pack2(lo_res(v.x), lo_res(v.y)), pack2(lo_res(v.z), lo_res(v.w)));
                    } else {
                        *(uint2*)(smem + OFF_BH + off) =
                            make_uint2(__float_as_uint(v.x), __float_as_uint(v.y));
                    }
                }
            }
        }
        if (trans) {
#pragma unroll
            for (int j = 0; j < 4; ++j) {
                const u32 off = (u32)(cN * 144 + (cK0 + j * 4) * 2);
                float v0 = pfBs[j * 4], v1 = pfBs[j * 4 + 1];
                float v2 = pfBs[j * 4 + 2], v3 = pfBs[j * 4 + 3];
                if (!fp16m) {
                    *(uint2*)(smem + OFF_BH + off) = make_uint2(pack2(v0, v1), pack2(v2, v3));
                    *(uint2*)(smem + OFF_BL + off) =
                        make_uint2(pack2(lo_res(v0), lo_res(v1)), pack2(lo_res(v2), lo_res(v3)));
                } else {
                    *(uint2*)(smem + OFF_BH + off) = make_uint2(pack2h(v0, v1), pack2h(v2, v3));
                }
            }
        }
        __syncthreads();
        if (c + 1 < nc) prefetch(c + 1);
        // ---- compute ----
        const int ns = kc >> 4;
        if (fp16m) {
            for (int ks = 0; ks < ns; ++ks) {
                const u32 kbyte = (u32)(ks * 32);
                u32 bh[2][4];
#pragma unroll
                for (int pr = 0; pr < 2; ++pr)
                    ldsm4(bh[pr], sb + (u32)((wn * 32 + pr * 16 + lBr) * 144) + kbyte + lBc + OFF_BH);
#pragma unroll
                for (int mf = 0; mf < 2; ++mf) {
                    u32 ah[4];
                    ldsm4(ah, sb + (u32)((wm * 32 + mf * 16 + lAr) * 144) + kbyte + lAc + OFF_AH);
#pragma unroll
                    for (int nf = 0; nf < 4; ++nf)
                        mma_fp16(acc[mf][nf], ah, &bh[nf >> 1][(nf & 1) * 2]);
                }
            }
        } else {
            for (int ks = 0; ks < ns; ++ks) {
                const u32 kbyte = (u32)(ks * 32);
                u32 bh[2][4], bl[2][4];
#pragma unroll
                for (int pr = 0; pr < 2; ++pr) {
                    const u32 ba = sb + (u32)((wn * 32 + pr * 16 + lBr) * 144) + kbyte + lBc;
                    ldsm4(bh[pr], ba + OFF_BH);
                    ldsm4(bl[pr], ba + OFF_BL);
                }
#pragma unroll
                for (int mf = 0; mf < 2; ++mf) {
                    u32 ah[4], al[4];
                    const u32 aa = sb + (u32)((wm * 32 + mf * 16 + lAr) * 144) + kbyte + lAc;
                    ldsm4(ah, aa + OFF_AH);
                    ldsm4(al, aa + OFF_AL);
#pragma unroll
                    for (int nf = 0; nf < 4; ++nf) {
                        const u32* bhf = &bh[nf >> 1][(nf & 1) * 2];
                        const u32* blf = &bl[nf >> 1][(nf & 1) * 2];
                        mma_bf16(acc[mf][nf], ah, bhf);
                        mma_bf16(acc[mf][nf], ah, blf);
                        mma_bf16(acc[mf][nf], al, bhf);
                    }
                }
            }
        }
    }

    // ---------------- epilogue ----------------
    const float aeff = o.alpha * (o.alphaDev ? o.alphaDev[b] : 1.f);
    float* Cb = o.C + (long long)b * o.sC;
    const int mb = m0 + wm * 32 + (lane >> 2);
    const int cb = n0 + wn * 32 + (lane & 3) * 2;

    float zs[4] = {0.f, 0.f, 0.f, 0.f}, zq[4] = {0.f, 0.f, 0.f, 0.f};

#pragma unroll
    for (int mf = 0; mf < 2; ++mf) {
#pragma unroll
        for (int nf = 0; nf < 4; ++nf) {
            const int c  = cb + nf * 8;
            const int r1 = mb + mf * 16;
            const int r2 = r1 + 8;
            float d0 = acc[mf][nf][0], d1 = acc[mf][nf][1];
            float d2 = acc[mf][nf][2], d3 = acc[mf][nf][3];

            if (o.flags & 4) {
                const float* rm = o.aux + b * D;
                const float invM = 1.f / (float)M;
                const float rc0 = rm[c], rc1 = rm[c + 1];
                *(float2*)&Cb[(size_t)r1 * o.ldc + c] =
                    make_float2(d0 * invM - rm[r1] * rc0, d1 * invM - rm[r1] * rc1);
                *(float2*)&Cb[(size_t)r2 * o.ldc + c] =
                    make_float2(d2 * invM - rm[r2] * rc0, d3 * invM - rm[r2] * rc1);
            } else if (o.flags & 2) {
                float* C2b = (float*)o.aux + (long long)b * (long long)(D * D);
                float2 a1 = *(const float2*)&Ab[(size_t)r1 * o.lda + c];
                float2 a2 = *(const float2*)&Ab[(size_t)r2 * o.lda + c];
                *(float2*)&Cb[(size_t)r1 * o.ldc + c] =
                    make_float2(1.5f * a1.x - 0.5f * d0, 1.5f * a1.y - 0.5f * d1);
                *(float2*)&Cb[(size_t)r2 * o.ldc + c] =
                    make_float2(1.5f * a2.x - 0.5f * d2, 1.5f * a2.y - 0.5f * d3);
                float2 z1 = make_float2(-0.5f * a1.x, -0.5f * a1.y);
                float2 z2 = make_float2(-0.5f * a2.x, -0.5f * a2.y);
                if (r1 == c)     z1.x += 1.5f;
                if (r1 == c + 1) z1.y += 1.5f;
                if (r2 == c)     z2.x += 1.5f;
                if (r2 == c + 1) z2.y += 1.5f;
                *(float2*)&C2b[(size_t)r1 * o.ldc + c] = z1;
                *(float2*)&C2b[(size_t)r2 * o.ldc + c] = z2;
            } else {
                if (c >= o.Ndim) continue;
                float2 v1 = make_float2(aeff * d0, aeff * d1);
                float2 v2 = make_float2(aeff * d2, aeff * d3);
                if (o.gamma != 0.f) {
                    if (r1 == c)     v1.x += o.gamma;
                    if (r1 == c + 1) v1.y += o.gamma;
                    if (r2 == c)     v2.x += o.gamma;
                    if (r2 == c + 1) v2.y += o.gamma;
                }
                *(float2*)&Cb[(size_t)r1 * o.ldc + c] = v1;
                *(float2*)&Cb[(size_t)r2 * o.ldc + c] = v2;
                if (o.flags & 16) {
                    zs[mf * 2 + 0] += v1.x + v1.y;
                    zq[mf * 2 + 0] += v1.x * v1.x + v1.y * v1.y;
                    zs[mf * 2 + 1] += v2.x + v2.y;
                    zq[mf * 2 + 1] += v2.x * v2.x + v2.y * v2.y;
                }
            }
        }
    }

    if (o.flags & 16) {
        __syncthreads();
        float* sred = (float*)smem;     // 256 floats: [0:128) sums, [128:256) sumsq
        if (t < 128) { sred[t] = 0.f; sred[128 + t] = 0.f; }
        __syncthreads();
#pragma unroll
        for (int q = 0; q < 4; ++q) {
            const int lr = wm * 32 + (lane >> 2) + (q >> 1) * 16 + (q & 1) * 8;
            atomicAdd(&sred[lr], zs[q]);
            atomicAdd(&sred[128 + lr], zq[q]);
        }
        __syncthreads();
        if (t < 128) {
            atomicAdd(&g_bnsum[m0 + t], sred[t]);
            atomicAdd(&g_bnsq[m0 + t], sred[128 + t]);
        }
    }
}

// ---------------- zero BN accumulators -------------------------------------
__global__ void zero_stats() {
    g_bnsum[threadIdx.x] = 0.f;
    g_bnsq[threadIdx.x] = 0.f;
}

// ---------------- BN apply + ReLU -> fp16, row mean ------------------------
__global__ void bn_apply(const float* __restrict__ Z,
                         const float* __restrict__ gamma, const float* __restrict__ beta,
                         __half* __restrict__ Zh, float* __restrict__ rmean) {
    const int bd = blockIdx.x;
    const int d = bd & (D - 1);
    const float Ninv = 1.f / (float)(BATCH * M);
    const float mu = g_bnsum[d] * Ninv;
    const float var = g_bnsq[d] * Ninv - mu * mu;
    const float sc = rsqrtf(var + 1e-5f) * gamma[d];
    const float sh = beta[d] - mu * sc;
    const float* row = Z + (size_t)bd * M;
    __half* oh = Zh + (size_t)bd * M;
    float s = 0.f;
    for (int i = threadIdx.x; i < M; i += blockDim.x) {
        float v = fmaxf(row[i] * sc + sh, 0.f);
        oh[i] = __float2half(v);
        s += v;
    }
    __shared__ float sm[128];
    sm[threadIdx.x] = s;
    __syncthreads();
    for (int o = 64; o > 0; o >>= 1) {
        if (threadIdx.x < o) sm[threadIdx.x] += sm[threadIdx.x + o];
        __syncthreads();
    }
    if (threadIdx.x == 0) rmean[bd] = sm[0] * (1.f / (float)M);
}

// ---------------- power iteration; tau = lambda_max/2 ----------------------
__global__ void power_iter(const float* __restrict__ cov, float* __restrict__ tau,
                           float* __restrict__ stau) {
    const int b = blockIdx.x;
    const float* Cb = cov + (size_t)b * D * D;
    __shared__ float v[D];
    __shared__ float red[256];
    const int t = threadIdx.x;
    v[t] = 1.f;
    __syncthreads();
    float lam = 1.f;
    for (int it = 0; it < NPOW; ++it) {
        float w = 0.f;
#pragma unroll 8
        for (int j = 0; j < D; ++j) w = fmaf(Cb[(size_t)j * D + t], v[j], w);
        red[t] = w * w;
        __syncthreads();
        for (int o = 128; o > 0; o >>= 1) {
            if (t < o) red[t] += red[t + o];
            __syncthreads();
        }
        lam = sqrtf(red[0]);
        v[t] = w / fmaxf(lam, 1e-20f);
        __syncthreads();
    }
    if (t == 0) {
        float l = fmaxf(lam, 1e-12f) * 0.5f;
        tau[b] = l;
        stau[b] = sqrtf(l);
    }
}

// ---------------- fused init: Anorm, X, E ----------------------------------
__global__ void init_mats(const float* __restrict__ cov, const float* __restrict__ tau,
                          float* __restrict__ An, float* __restrict__ X,
                          float* __restrict__ E) {
    const int b = blockIdx.y, i = blockIdx.x;
    const float it = 1.f / tau[b];
    const size_t off = ((size_t)b * D + i) * D;
    for (int j = threadIdx.x; j < D; j += blockDim.x) {
        float c = cov[off + j];
        An[off + j] = c * it;
        float x = c * (-1.f / 64.f);
        X[off + j] = x;
        E[off + j] = 0.2f * x + ((i == j) ? 1.f : 0.f);
    }
}

// ---------------- Frobenius norm per batch ---------------------------------
__global__ void frob_norm(const float* __restrict__ A, float* __restrict__ out) {
    const int b = blockIdx.x;
    const float* Ab = A + (size_t)b * D * D;
    float ss = 0.f;
    for (int i = threadIdx.x; i < D * D; i += 256) {
        float v = Ab[i];
        ss += v * v;
    }
    __shared__ float sm[256];
    sm[threadIdx.x] = ss;
    __syncthreads();
    for (int o = 128; o > 0; o >>= 1) {
        if (threadIdx.x < o) sm[threadIdx.x] += sm[threadIdx.x + o];
        __syncthreads();
    }
    if (threadIdx.x == 0) out[b] = fmaxf(sqrtf(sm[0]), 1e-12f);
}

__global__ void out_triu(const float* __restrict__ Sq, const float* __restrict__ nrm,
                         float* __restrict__ out) {
    const int b = blockIdx.y, i = blockIdx.x;
    const float sc = 1.f + nrm[b];
    const size_t rowoff = (size_t)i * D - (size_t)i * (i - 1) / 2;
    const float* row = Sq + ((size_t)b * D + i) * D;
    float* ob = out + (size_t)b * (D * (D + 1) / 2) + rowoff - i;
    for (int j = i + (int)threadIdx.x; j < D; j += blockDim.x) ob[j] = sc * row[j];
}

// ---------------------------------------------------------------------------
static float* sym_addr(const void* symbol) {
    void* p = nullptr;
    cudaGetSymbolAddress(&p, symbol);
    return (float*)p;
}

static OpDesc mkop(const float* A, const float* B, float* C, float alpha,
                   float gamma, int K, int lda, int ldb, int ldc, int Ndim, int flags,
                   const float* aux = nullptr, const float* alphaDev = nullptr,
                   long long sA = (long long)D * D, long long sB = (long long)D * D,
                   long long sC = (long long)D * D) {
    OpDesc o;
    o.A = A; o.B = B; o.C = C; o.aux = aux; o.alphaDev = alphaDev;
    o.sA = sA; o.sB = sB; o.sC = sC;
    o.alpha = alpha; o.gamma = gamma;
    o.K = K; o.lda = lda; o.ldb = ldb; o.ldc = ldc; o.Ndim = Ndim; o.flags = flags;
    return o;
}

extern "C" void kernel_launch(void* const* d_in, const int* in_sizes, int n_in,
                              void* d_out, int out_size) {
    const float* x  = (const float*)d_in[0];
    const float* w  = (const float*)d_in[1];
    const float* gm = (const float*)d_in[2];
    const float* bt = (const float*)d_in[3];
    float* out = (float*)d_out;

    float* Z    = sym_addr(g_Z);
    float* Zh   = sym_addr(g_Zh);     // __half*, cast where needed
    float* cov  = sym_addr(g_cov);
    float* Y    = sym_addr(g_Y);
    float* Y2   = sym_addr(g_Y2);
    float* Zm   = sym_addr(g_Zm);
    float* Z2   = sym_addr(g_Z2);
    float* T    = sym_addr(g_T);
    float* E    = sym_addr(g_E);
    float* E2   = sym_addr(g_E2);
    float* rmn  = sym_addr(g_rmean);
    float* tau  = sym_addr(g_tau);
    float* stau = sym_addr(g_stau);
    float* nrm  = sym_addr(g_nrm);

    cudaFuncSetAttribute(tc_gemm, cudaFuncAttributeMaxDynamicSharedMemorySize, SMEM_BYTES);

    // expm op sequencer: 4 Taylor (k=4..1) + 6 squarings
    float* Xb = Z;          // X = -cov/64 reuses g_Z after activations retire
    float* Ec = E; float* En = E2;
    int expmStage = 0;
    auto nextExpmOp = [&](OpDesc* slot) -> bool {
        if (expmStage >= 10) return false;
        if (expmStage < 4) {
            float kinv = 1.f / (float)(4 - expmStage);
            *slot = mkop(Xb, Ec, En, kinv, 1.f, D, D, D, D, D, 0);
        } else {
            *slot = mkop(Ec, Ec, En, 1.f, 0.f, D, D, D, D, D, 0);
        }
        std::swap(Ec, En);
        ++expmStage;
        return true;
    };

    OpDesc dummy = mkop(cov, cov, T, 0.f, 0.f, D, D, D, D, D, 0);

    auto launch = [&](OpDesc* ops, int n) {
        tc_gemm<<<dim3(4, 2, 32 * n), 256, SMEM_BYTES>>>(ops[0], n > 1 ? ops[1] : dummy,
                                                         n > 2 ? ops[2] : dummy);
    };

    // 0. zero BN stat accumulators
    zero_stats<<<1, D>>>();
    // 1. conv 1x1 (fp16 single-MMA) with fused BN-stat accumulation
    {
        OpDesc c = mkop(w, x, Z, 1.f, 0.f, CIN, CIN, M, M, M, 1 | 8 | 16,
                        nullptr, nullptr, 0LL, (long long)CIN * M, (long long)D * M);
        tc_gemm<<<dim3(13, 2, 32), 256, SMEM_BYTES>>>(c, dummy, dummy);
    }
    // 2. BN apply + ReLU -> fp16 Zh + rmean
    bn_apply<<<BATCH * D, 128>>>(Z, gm, bt, (__half*)Zh, rmn);
    // 3. covariance (fp16 single-MMA): cov = Zh Zh^T / M - rmean rmean^T
    {
        OpDesc c = mkop(Zh, Zh, cov, 1.f, 0.f, M, M, M, D, D, 8 | 4,
                        rmn, nullptr, (long long)D * M, (long long)D * M, (long long)D * D);
        launch(&c, 1);
    }
    // 4. spectral norm -> tau = lam/2
    power_iter<<<BATCH, 256>>>(cov, tau, stau);
    // 5. fused inits (Anorm->Y, X->g_Z, E)
    init_mats<<<dim3(D, BATCH), 256>>>(cov, tau, Y, Xb, E);

    // 6. round 1: NSFIRST (S=A^2 -> Y1,Z1) + expm rider
    {
        OpDesc ops[3]; int n = 0;
        ops[n++] = mkop(Y, Y, Y2, 1.f, 0.f, D, D, D, D, D, 2, Zm);
        if (nextExpmOp(&ops[n])) ++n;
        launch(ops, n);
    }
    float *Yc = Y2, *Zc = Zm, *Yn = Y, *Zn = Z2;
    float* Sq = nullptr;

    // 7. NS iterations 2..NNS with expm riders
    for (int it = 2; it <= NNS; ++it) {
        {   // round A: T = 3I - Z@Y (+ rider)
            OpDesc ops[3]; int n = 0;
            ops[n++] = mkop(Zc, Yc, T, -1.f, 3.f, D, D, D, D, D, 0);
            if (nextExpmOp(&ops[n])) ++n;
            launch(ops, n);
        }
        {   // round B (+ rider)
            OpDesc ops[3]; int n = 0;
            if (it < NNS) {
                ops[n++] = mkop(Yc, T, Yn, 0.5f, 0.f, D, D, D, D, D, 0);
                ops[n++] = mkop(T, Zc, Zn, 0.5f, 0.f, D, D, D, D, D, 0);
            } else {
                ops[n++] = mkop(Yc, T, Yn, 0.5f, 0.f, D, D, D, D, D, 0, nullptr, stau);
                Sq = Yn;
            }
            if (n < 3 && nextExpmOp(&ops[n])) ++n;
            launch(ops, n);
            std::swap(Yc, Yn); std::swap(Zc, Zn);
        }
    }
    // safety drain
    while (expmStage < 10) {
        OpDesc ops[3]; int n = 0;
        nextExpmOp(&ops[n]); ++n;
        launch(ops, n);
    }

    // 8. P = Sq @ E -> T, nrm = ||P||_F
    {
        OpDesc p = mkop(Sq, Ec, T, 1.f, 0.f, D, D, D, D, D, 0);
        launch(&p, 1);
    }
    frob_norm<<<BATCH, 256>>>(T, nrm);
    // 9. output
    out_triu<<<dim3(D, BATCH), 256>>>(Sq, nrm, out);

    (void)in_sizes; (void)n_in; (void)out_size;
}